// round 13
// baseline (speedup 1.0000x reference)
#include <cuda_runtime.h>
#include <cuda_fp16.h>
#include <cstdint>

// Problem constants
#define Bq   4
#define Tq   4096
#define Cq   2048
#define Hq   16
#define DHq  128
#define Mq   (Bq*Tq)          // 16384
#define BHq  (Bq*Hq)          // 64

// -------- device globals (allocation-free rule) --------
__device__ __half g_xh[Mq*Cq];     // x hi [m][c]
__device__ __half g_wh[4*Cq*Cq];   // Wq|Wk|Wv|Wo hi/lo [o][c]
__device__ __half g_wl[4*Cq*Cq];
__device__ __half g_qh[Mq*Cq];     // q hi/lo [bh][t][d]
__device__ __half g_ql[Mq*Cq];
__device__ __half g_kth[Mq*Cq];    // kT hi/lo [bh][d][t]
__device__ __half g_ktl[Mq*Cq];
__device__ __half g_vth[Mq*Cq];    // vT hi/lo [bh][d][t]
__device__ __half g_vtl[Mq*Cq];
__device__ float  g_kvp[4*BHq*DHq*DHq];  // kv split-T fp32 partials
__device__ __half g_kvh[BHq*DHq*DHq];    // kvT[e][d] hi/lo
__device__ __half g_kvl[BHq*DHq*DHq];
__device__ __half g_ath[Mq*Cq];    // attention out hi [b,t,C]
__device__ float  g_ksum[BHq*DHq];

__device__ __forceinline__ float featmap(float y) {
    return y > 0.f ? y + 1.f : __expf(y);   // elu(y)+1
}

__device__ __forceinline__ uint32_t smem_u32(const void* p) {
    uint32_t a;
    asm("{ .reg .u64 t; cvta.to.shared.u64 t, %1; cvt.u32.u64 %0, t; }"
        : "=r"(a) : "l"(p));
    return a;
}

__device__ __forceinline__ void cpa16(uint32_t s, const void* g) {
    asm volatile("cp.async.cg.shared.global [%0], [%1], 16;" :: "r"(s), "l"(g));
}

#define LDSM4(r, a)                                                            \
    asm volatile("ldmatrix.sync.aligned.m8n8.x4.shared.b16 {%0,%1,%2,%3}, [%4];" \
        : "=r"((r)[0]), "=r"((r)[1]), "=r"((r)[2]), "=r"((r)[3]) : "r"(a))

__device__ __forceinline__ void mma16816(float* d, const uint32_t* a, const uint32_t* b)
{
    asm volatile(
        "mma.sync.aligned.m16n8k16.row.col.f32.f16.f16.f32 "
        "{%0,%1,%2,%3}, {%4,%5,%6,%7}, {%8,%9}, {%0,%1,%2,%3};"
        : "+f"(d[0]), "+f"(d[1]), "+f"(d[2]), "+f"(d[3])
        : "r"(a[0]), "r"(a[1]), "r"(a[2]), "r"(a[3]), "r"(b[0]), "r"(b[1]));
}

// ===========================================================================
// fp32 -> (hi, lo) fp16 split elementwise.
// ===========================================================================
__global__ void cvt_kernel(const float* __restrict__ src, int dst_sel, int n4)
{
    const int i = blockIdx.x * blockDim.x + threadIdx.x;
    if (i >= n4) return;
    float4 v = ((const float4*)src)[i];
    __half2 h0 = __floats2half2_rn(v.x, v.y);
    __half2 h1 = __floats2half2_rn(v.z, v.w);
    if (dst_sel == 0) {
        ((__half2*)g_xh)[i*2]   = h0;
        ((__half2*)g_xh)[i*2+1] = h1;
        return;
    }
    __half* hi = g_wh + (size_t)(dst_sel - 1) * Cq * Cq;
    __half* lo = g_wl + (size_t)(dst_sel - 1) * Cq * Cq;
    float2  b0 = __half22float2(h0);
    __half2 l0 = __floats2half2_rn(v.x - b0.x, v.y - b0.y);
    float2  b1 = __half22float2(h1);
    __half2 l1 = __floats2half2_rn(v.z - b1.x, v.w - b1.y);
    ((__half2*)hi)[i*2]   = h0;  ((__half2*)hi)[i*2+1] = h1;
    ((__half2*)lo)[i*2]   = l0;  ((__half2*)lo)[i*2+1] = l1;
}

__global__ void zero_ksum_kernel()
{
    const int i = blockIdx.x * blockDim.x + threadIdx.x;
    if (i < BHq*DHq) g_ksum[i] = 0.f;
}

#define SMEM_BIG     131072               // 4 stages x 32KB
#define GEMM_SMEM    98304                // 3 stages x 32KB (small core)
#define TPITCH       136

// ===========================================================================
// BIG core: 256x128 CTA, 512 threads (16 warps, 4m x 4n), BK=32, 2-product.
// 4-stage cp.async pipeline (prefetch distance 3).
// EPI: 0 = fp32 out; 1 = featmap -> q hi/lo [bh][t][d];
//      2 = (act?) -> transpose -> hi/lo [bh][d][t]; do_ks: ksum atomics (K only)
// ===========================================================================
template<int EPI>
__device__ __forceinline__ void mma_big(
    const __half* __restrict__ Ah_g,
    const __half* __restrict__ Bh_g, const __half* __restrict__ Bl_g,
    int lda, int ldb, int bmG, int bn, int bh,
    float* __restrict__ out_f32, __half* __restrict__ outh,
    __half* __restrict__ outl, bool act, bool do_ks)
{
    extern __shared__ char sm2[];
    const uint32_t sb = smem_u32(sm2);
    const int tid = threadIdx.x;

    const int rowG = tid >> 1;
    const int seg0 = (tid & 1) * 2;
    const uint32_t xrg = ((rowG >> 1) & 3) << 4;
    const uint32_t d0 = rowG*64 + (( seg0   *16) ^ xrg);
    const uint32_t d1 = rowG*64 + (((seg0+1)*16) ^ xrg);
    const __half* sA = Ah_g + (size_t)(bmG + rowG) * lda + seg0*8;
    const __half* sB = (rowG < 128)
        ? Bh_g + (size_t)(bn + rowG)       * ldb + seg0*8
        : Bl_g + (size_t)(bn + rowG - 128) * ldb + seg0*8;

    auto issue = [&](int kc, int slot) {
        const uint32_t b = sb + slot * 32768u;
        const int ko = kc * 32;
        cpa16(b          + d0, sA + ko);  cpa16(b          + d1, sA + ko + 8);
        cpa16(b + 16384u + d0, sB + ko);  cpa16(b + 16384u + d1, sB + ko + 8);
        asm volatile("cp.async.commit_group;" ::: "memory");
    };

    issue(0, 0);
    issue(1, 1);
    issue(2, 2);

    const int wid  = tid >> 5;
    const int lane = tid & 31;
    const int wm = (wid & 3) * 64;
    const int wn = (wid >> 2) * 32;
    const uint32_t xs  = ((lane >> 1) & 3) << 4;
    const uint32_t kqa = (lane >> 4) * 16;
    const uint32_t kqb = ((lane >> 3) & 1) * 16;
    uint32_t saofs[4], sbofs[2];
    #pragma unroll
    for (int mt = 0; mt < 4; mt++)
        saofs[mt] = (uint32_t)(wm + mt*16 + (lane & 15)) * 64;
    #pragma unroll
    for (int p = 0; p < 2; p++)
        sbofs[p] = (uint32_t)(wn + p*16 + ((lane >> 4) & 1)*8 + (lane & 7)) * 64;

    float acc[4][4][4];
    #pragma unroll
    for (int i = 0; i < 4; i++)
        #pragma unroll
        for (int j = 0; j < 4; j++)
            #pragma unroll
            for (int e = 0; e < 4; e++) acc[i][j][e] = 0.f;

    const int NCHUNK = Cq / 32;   // 64

    for (int kc = 0; kc < NCHUNK; kc++) {
        if (kc <= NCHUNK - 3)      asm volatile("cp.async.wait_group 2;" ::: "memory");
        else if (kc == NCHUNK - 2) asm volatile("cp.async.wait_group 1;" ::: "memory");
        else                       asm volatile("cp.async.wait_group 0;" ::: "memory");
        __syncthreads();
        if (kc + 3 < NCHUNK) issue(kc + 3, (kc + 3) & 3);

        const uint32_t st = sb + (kc & 3) * 32768u;
        #pragma unroll
        for (int ks = 0; ks < 2; ks++) {
            uint32_t ah[4][4];
            const uint32_t ca = (ks*32 + kqa) ^ xs;
            #pragma unroll
            for (int mt = 0; mt < 4; mt++)
                LDSM4(ah[mt], st + saofs[mt] + ca);
            const uint32_t cb = (ks*32 + kqb) ^ xs;
            #pragma unroll
            for (int p = 0; p < 2; p++) {
                uint32_t bh2[4], bl2[4];
                LDSM4(bh2, st + 16384u + sbofs[p] + cb);
                LDSM4(bl2, st + 24576u + sbofs[p] + cb);
                #pragma unroll
                for (int mt = 0; mt < 4; mt++) {
                    mma16816(acc[mt][2*p],   ah[mt], bh2);
                    mma16816(acc[mt][2*p],   ah[mt], bl2);
                    mma16816(acc[mt][2*p+1], ah[mt], bh2 + 2);
                    mma16816(acc[mt][2*p+1], ah[mt], bl2 + 2);
                }
            }
        }
    }

    const int r0 = lane >> 2;
    const int c0 = (lane & 3) * 2;

    if constexpr (EPI == 2) {
        __syncthreads();
        __half* shh = (__half*)sm2;
        __half* shl = shh + 128*TPITCH;
        const int myhh = (wid & 3) >> 1;
        const int dd = tid >> 2;
        const int ts = (tid & 3) * 32;
        float ksacc = 0.f;
        #pragma unroll
        for (int hh = 0; hh < 2; hh++) {
            if (myhh == hh) {
                #pragma unroll
                for (int mt = 0; mt < 4; mt++)
                    #pragma unroll
                    for (int half = 0; half < 2; half++) {
                        const int lt = (wm + mt*16 + r0 + half*8) & 127;
                        #pragma unroll
                        for (int nt = 0; nt < 4; nt++) {
                            const int n0 = wn + nt*8 + c0;
                            float v0 = acc[mt][nt][half*2];
                            float v1 = acc[mt][nt][half*2 + 1];
                            if (act) { v0 = featmap(v0); v1 = featmap(v1); }
                            __half h0 = __float2half_rn(v0);
                            __half h1 = __float2half_rn(v1);
                            __half l0 = __float2half_rn(v0 - __half2float(h0));
                            __half l1 = __float2half_rn(v1 - __half2float(h1));
                            shh[ n0   *TPITCH + lt] = h0;
                            shh[(n0+1)*TPITCH + lt] = h1;
                            shl[ n0   *TPITCH + lt] = l0;
                            shl[(n0+1)*TPITCH + lt] = l1;
                        }
                    }
            }
            __syncthreads();
            const int tdst = (bmG & (Tq - 1)) + hh*128 + ts;
            const uint4* srcH = (const uint4*)(shh + dd*TPITCH + ts);
            const uint4* srcL = (const uint4*)(shl + dd*TPITCH + ts);
            uint4* dstH = (uint4*)(outh + ((size_t)bh*DHq + dd)*Tq + tdst);
            uint4* dstL = (uint4*)(outl + ((size_t)bh*DHq + dd)*Tq + tdst);
            #pragma unroll
            for (int q = 0; q < 4; q++) {
                uint4 h4 = srcH[q], l4 = srcL[q];
                dstH[q] = h4; dstL[q] = l4;
                if (do_ks) {
                    const __half2* hp = (const __half2*)&h4;
                    const __half2* lp = (const __half2*)&l4;
                    #pragma unroll
                    for (int e = 0; e < 4; e++) {
                        float2 a = __half22float2(hp[e]);
                        float2 b = __half22float2(lp[e]);
                        ksacc += a.x + a.y + b.x + b.y;
                    }
                }
            }
            __syncthreads();
        }
        if (do_ks) atomicAdd(&g_ksum[bh*DHq + dd], ksacc);
        return;
    }

    #pragma unroll
    for (int mt = 0; mt < 4; mt++) {
        #pragma unroll
        for (int half = 0; half < 2; half++) {
            const int lm = wm + mt*16 + r0 + half*8;
            #pragma unroll
            for (int nt = 0; nt < 4; nt++) {
                const int n0 = wn + nt*8 + c0;
                float v0 = acc[mt][nt][half*2];
                float v1 = acc[mt][nt][half*2 + 1];
                if constexpr (EPI == 0) {
                    float* op = out_f32 + (size_t)(bmG + lm) * Cq + bn;
                    *(float2*)(op + n0) = make_float2(v0, v1);
                } else if constexpr (EPI == 1) {
                    if (act) { v0 = featmap(v0); v1 = featmap(v1); }
                    const int t = (bmG + lm) & (Tq - 1);
                    const size_t base = ((size_t)bh*Tq + t)*DHq;
                    __half2 h2 = __floats2half2_rn(v0, v1);
                    float2  bk = __half22float2(h2);
                    __half2 l2 = __floats2half2_rn(v0 - bk.x, v1 - bk.y);
                    *(__half2*)&outh[base + n0] = h2;
                    *(__half2*)&outl[base + n0] = l2;
                }
            }
        }
    }
}

// ===========================================================================
// Small 128x128 3-product core.
// EPI 4 = attn (z computed in-kernel from ksum), EPI 5 = kv fp32 partial.
// ===========================================================================
template<int EPI>
__device__ __forceinline__ void mma_core(
    const __half* __restrict__ Ah_g, const __half* __restrict__ Al_g,
    const __half* __restrict__ Bh_g, const __half* __restrict__ Bl_g,
    int lda, int ldb, int Klen, int koff, int bm, int bn, int bh,
    float* __restrict__ out_f32, __half* __restrict__ outh,
    const float* __restrict__ kss)
{
    extern __shared__ char sm2[];
    const uint32_t sb = smem_u32(sm2);
    const int tid = threadIdx.x;

    const int rowG = tid >> 1;
    const int seg0 = (tid & 1) * 2;
    const uint32_t xrg = ((rowG >> 1) & 3) << 4;
    const uint32_t d0 = rowG*64 + (( seg0   *16) ^ xrg);
    const uint32_t d1 = rowG*64 + (((seg0+1)*16) ^ xrg);
    const __half* sAh = Ah_g + (size_t)(bm + rowG) * lda + seg0*8 + koff;
    const __half* sAl = Al_g + (size_t)(bm + rowG) * lda + seg0*8 + koff;
    const __half* sBh = Bh_g + (size_t)(bn + rowG) * ldb + seg0*8 + koff;
    const __half* sBl = Bl_g + (size_t)(bn + rowG) * ldb + seg0*8 + koff;

    auto issue = [&](int kc, int slot) {
        const uint32_t b = sb + slot * 32768u;
        const int ko = kc * 32;
        cpa16(b          + d0, sAh + ko);  cpa16(b          + d1, sAh + ko + 8);
        cpa16(b +  8192u + d0, sAl + ko);  cpa16(b +  8192u + d1, sAl + ko + 8);
        cpa16(b + 16384u + d0, sBh + ko);  cpa16(b + 16384u + d1, sBh + ko + 8);
        cpa16(b + 24576u + d0, sBl + ko);  cpa16(b + 24576u + d1, sBl + ko + 8);
        asm volatile("cp.async.commit_group;" ::: "memory");
    };

    issue(0, 0);
    issue(1, 1);

    const int wid  = tid >> 5;
    const int lane = tid & 31;
    const int wm = (wid & 3) * 32;
    const int wn = (wid >> 2) * 64;
    const uint32_t xs  = ((lane >> 1) & 3) << 4;
    const uint32_t kqa = (lane >> 4) * 16;
    const uint32_t kqb = ((lane >> 3) & 1) * 16;
    uint32_t saofs[2], sbofs[4];
    #pragma unroll
    for (int mt = 0; mt < 2; mt++)
        saofs[mt] = (uint32_t)(wm + mt*16 + (lane & 15)) * 64;
    #pragma unroll
    for (int p = 0; p < 4; p++)
        sbofs[p] = (uint32_t)(wn + p*16 + ((lane >> 4) & 1)*8 + (lane & 7)) * 64;

    float acc[2][8][4];
    #pragma unroll
    for (int i = 0; i < 2; i++)
        #pragma unroll
        for (int j = 0; j < 8; j++)
            #pragma unroll
            for (int e = 0; e < 4; e++) acc[i][j][e] = 0.f;

    const int NCHUNK = Klen / 32;

    for (int kc = 0; kc < NCHUNK; kc++) {
        if (kc == NCHUNK - 1) asm volatile("cp.async.wait_group 0;" ::: "memory");
        else                  asm volatile("cp.async.wait_group 1;" ::: "memory");
        __syncthreads();
        if (kc + 2 < NCHUNK) issue(kc + 2, (kc + 2) % 3);

        const uint32_t st = sb + (kc % 3) * 32768u;
        #pragma unroll
        for (int ks = 0; ks < 2; ks++) {
            uint32_t ah[2][4], al[2][4];
            const uint32_t ca = (ks*32 + kqa) ^ xs;
            #pragma unroll
            for (int mt = 0; mt < 2; mt++) {
                LDSM4(ah[mt], st + saofs[mt] + ca);
                LDSM4(al[mt], st + 8192u + saofs[mt] + ca);
            }
            const uint32_t cb = (ks*32 + kqb) ^ xs;
            #pragma unroll
            for (int p = 0; p < 4; p++) {
                uint32_t bh2[4], bl2[4];
                LDSM4(bh2, st + 16384u + sbofs[p] + cb);
                LDSM4(bl2, st + 24576u + sbofs[p] + cb);
                #pragma unroll
                for (int mt = 0; mt < 2; mt++) {
                    mma16816(acc[mt][2*p],   ah[mt], bh2);
                    mma16816(acc[mt][2*p],   ah[mt], bl2);
                    mma16816(acc[mt][2*p],   al[mt], bh2);
                    mma16816(acc[mt][2*p+1], ah[mt], bh2 + 2);
                    mma16816(acc[mt][2*p+1], ah[mt], bl2 + 2);
                    mma16816(acc[mt][2*p+1], al[mt], bh2 + 2);
                }
            }
        }
    }

    const int r0 = lane >> 2;
    const int c0 = (lane & 3) * 2;

    if constexpr (EPI == 4) {
        // z-phase: zs[t] = 1/(q[t]·ksum + 1e-6)
        __syncthreads();
        float* zs = (float*)sm2;
        if (tid < 128) {
            const __half2* qh2 = (const __half2*)(Ah_g + (size_t)(bm + tid)*lda);
            const __half2* ql2 = (const __half2*)(Al_g + (size_t)(bm + tid)*lda);
            const float2* kf = (const float2*)kss;
            float s = 0.f;
            #pragma unroll 16
            for (int i = 0; i < 64; i++) {
                float2 a = __half22float2(qh2[i]);
                float2 b = __half22float2(ql2[i]);
                float2 k2 = kf[i];
                s += (a.x + b.x) * k2.x + (a.y + b.y) * k2.y;
            }
            zs[tid] = 1.f / (s + 1e-6f);
        }
        __syncthreads();
        #pragma unroll
        for (int mt = 0; mt < 2; mt++)
            #pragma unroll
            for (int half = 0; half < 2; half++) {
                const int lm = wm + mt*16 + r0 + half*8;
                const float z = zs[lm];
                const int t = bm + lm;
                const size_t base =
                    ((size_t)(bh >> 4)*Tq + t)*Cq + (size_t)(bh & 15)*DHq;
                #pragma unroll
                for (int nt = 0; nt < 8; nt++) {
                    const int n0 = wn + nt*8 + c0;
                    *(__half2*)&outh[base + n0] =
                        __floats2half2_rn(acc[mt][nt][half*2] * z,
                                          acc[mt][nt][half*2 + 1] * z);
                }
            }
        return;
    }

    // EPI == 5: fp32 partial, pitch DHq
    #pragma unroll
    for (int mt = 0; mt < 2; mt++)
        #pragma unroll
        for (int half = 0; half < 2; half++) {
            const int lm = wm + mt*16 + r0 + half*8;
            #pragma unroll
            for (int nt = 0; nt < 8; nt++) {
                const int n0 = wn + nt*8 + c0;
                *(float2*)(out_f32 + (size_t)lm*DHq + n0) =
                    make_float2(acc[mt][nt][half*2], acc[mt][nt][half*2 + 1]);
            }
        }
}

// ---------------------------------------------------------------------------
// kernels
// ---------------------------------------------------------------------------
__global__ __launch_bounds__(512, 1)
void qkv_mma_kernel()
{
    const int h   = blockIdx.x;
    const int bmG = blockIdx.y * 256;
    const int z   = blockIdx.z;
    const int bh  = ((bmG >> 12) << 4) + h;
    const __half* Wh = g_wh + (size_t)z * Cq * Cq;
    const __half* Wl = g_wl + (size_t)z * Cq * Cq;
    if (z == 0)
        mma_big<1>(g_xh, Wh, Wl, Cq, Cq, bmG, h*128, bh,
                   nullptr, g_qh, g_ql, true, false);
    else if (z == 1)
        mma_big<2>(g_xh, Wh, Wl, Cq, Cq, bmG, h*128, bh,
                   nullptr, g_kth, g_ktl, true, true);
    else
        mma_big<2>(g_xh, Wh, Wl, Cq, Cq, bmG, h*128, bh,
                   nullptr, g_vth, g_vtl, false, false);
}

__global__ __launch_bounds__(512, 1)
void out_mma_kernel(float* __restrict__ out)
{
    mma_big<0>(g_ath, g_wh + (size_t)3*Cq*Cq, g_wl + (size_t)3*Cq*Cq,
               Cq, Cq, blockIdx.y*256, blockIdx.x*128, 0,
               out, nullptr, nullptr, false, false);
}

__global__ __launch_bounds__(256, 2)
void kv_part_kernel()
{
    const int bh = blockIdx.x;
    const int p  = blockIdx.y;
    const size_t o = (size_t)bh * DHq * Tq;
    float* outp = g_kvp + ((size_t)p*BHq + bh) * DHq * DHq;
    mma_core<5>(g_vth + o, g_vtl + o, g_kth + o, g_ktl + o,
                Tq, Tq, 1024, p*1024, 0, 0, bh, outp, nullptr, nullptr);
}

__global__ void kv_reduce_kernel()
{
    const int i = blockIdx.x * blockDim.x + threadIdx.x;   // pair index
    const int base = i * 2;
    float s0 = 0.f, s1 = 0.f;
    #pragma unroll
    for (int p = 0; p < 4; p++) {
        const float2 v = *(const float2*)&g_kvp[(size_t)p*BHq*DHq*DHq + base];
        s0 += v.x; s1 += v.y;
    }
    __half2 h2 = __floats2half2_rn(s0, s1);
    float2  bk = __half22float2(h2);
    __half2 l2 = __floats2half2_rn(s0 - bk.x, s1 - bk.y);
    *(__half2*)&g_kvh[base] = h2;
    *(__half2*)&g_kvl[base] = l2;
}

__global__ __launch_bounds__(256, 2)
void attn_mma_kernel()
{
    const int bh = blockIdx.x;
    const int bm = blockIdx.y * 128;
    const size_t oq = (size_t)bh * Tq * DHq;
    const size_t ok = (size_t)bh * DHq * DHq;
    mma_core<4>(g_qh + oq, g_ql + oq, g_kvh + ok, g_kvl + ok,
                DHq, DHq, DHq, 0, bm, 0, bh,
                nullptr, g_ath, g_ksum + bh*DHq);
}

// ---------------------------------------------------------------------------
extern "C" void kernel_launch(void* const* d_in, const int* in_sizes, int n_in,
                              void* d_out, int out_size)
{
    const float* x  = (const float*)d_in[0];
    // d_in[1] = cos, d_in[2] = sin : unused by the reference module
    const float* Wq = (const float*)d_in[3];
    const float* Wk = (const float*)d_in[4];
    const float* Wv = (const float*)d_in[5];
    const float* Wo = (const float*)d_in[6];
    float* out = (float*)d_out;

    cudaFuncSetAttribute(qkv_mma_kernel,
                         cudaFuncAttributeMaxDynamicSharedMemorySize, SMEM_BIG);
    cudaFuncSetAttribute(out_mma_kernel,
                         cudaFuncAttributeMaxDynamicSharedMemorySize, SMEM_BIG);
    cudaFuncSetAttribute(kv_part_kernel,
                         cudaFuncAttributeMaxDynamicSharedMemorySize, GEMM_SMEM);
    cudaFuncSetAttribute(attn_mma_kernel,
                         cudaFuncAttributeMaxDynamicSharedMemorySize, GEMM_SMEM);

    zero_ksum_kernel<<<(BHq*DHq + 255)/256, 256>>>();
    cvt_kernel<<<(Mq*Cq/4 + 255)/256, 256>>>(x,  0, Mq*Cq/4);
    cvt_kernel<<<(Cq*Cq/4 + 255)/256, 256>>>(Wq, 1, Cq*Cq/4);
    cvt_kernel<<<(Cq*Cq/4 + 255)/256, 256>>>(Wk, 2, Cq*Cq/4);
    cvt_kernel<<<(Cq*Cq/4 + 255)/256, 256>>>(Wv, 3, Cq*Cq/4);
    cvt_kernel<<<(Cq*Cq/4 + 255)/256, 256>>>(Wo, 4, Cq*Cq/4);

    qkv_mma_kernel<<<dim3(Hq, Mq/256, 3), 512, SMEM_BIG>>>();
    kv_part_kernel<<<dim3(BHq, 4), 256, GEMM_SMEM>>>();
    kv_reduce_kernel<<<BHq*DHq*DHq/2/256, 256>>>();
    attn_mma_kernel<<<dim3(BHq, Tq/128), 256, GEMM_SMEM>>>();
    out_mma_kernel<<<dim3(Cq/128, Mq/256), 512, SMEM_BIG>>>(out);
}

// round 14
// speedup vs baseline: 1.0022x; 1.0022x over previous
#include <cuda_runtime.h>
#include <cuda_fp16.h>
#include <cstdint>

// Problem constants
#define Bq   4
#define Tq   4096
#define Cq   2048
#define Hq   16
#define DHq  128
#define Mq   (Bq*Tq)          // 16384
#define BHq  (Bq*Hq)          // 64

// -------- device globals (allocation-free rule) --------
__device__ __half g_xh[Mq*Cq];     // x hi [m][c]
__device__ __half g_wh[4*Cq*Cq];   // Wq|Wk|Wv|Wo hi/lo [o][c]
__device__ __half g_wl[4*Cq*Cq];
__device__ __half g_qh[Mq*Cq];     // q hi/lo [bh][t][d]
__device__ __half g_ql[Mq*Cq];
__device__ __half g_kth[Mq*Cq];    // kT hi/lo [bh][d][t]
__device__ __half g_ktl[Mq*Cq];
__device__ __half g_vth[Mq*Cq];    // vT hi/lo [bh][d][t]
__device__ __half g_vtl[Mq*Cq];
__device__ float  g_kvp[4*BHq*DHq*DHq];  // kv split-T fp32 partials
__device__ __half g_kvh[BHq*DHq*DHq];    // kvT[e][d] hi/lo
__device__ __half g_kvl[BHq*DHq*DHq];
__device__ __half g_ath[Mq*Cq];    // attention out hi [b,t,C]
__device__ float  g_ksum[BHq*DHq];

__device__ __forceinline__ float featmap(float y) {
    return y > 0.f ? y + 1.f : __expf(y);   // elu(y)+1
}

__device__ __forceinline__ uint32_t smem_u32(const void* p) {
    uint32_t a;
    asm("{ .reg .u64 t; cvta.to.shared.u64 t, %1; cvt.u32.u64 %0, t; }"
        : "=r"(a) : "l"(p));
    return a;
}

__device__ __forceinline__ void cpa16(uint32_t s, const void* g) {
    asm volatile("cp.async.cg.shared.global [%0], [%1], 16;" :: "r"(s), "l"(g));
}

#define LDSM4(r, a)                                                            \
    asm volatile("ldmatrix.sync.aligned.m8n8.x4.shared.b16 {%0,%1,%2,%3}, [%4];" \
        : "=r"((r)[0]), "=r"((r)[1]), "=r"((r)[2]), "=r"((r)[3]) : "r"(a))

__device__ __forceinline__ void mma16816(float* d, const uint32_t* a, const uint32_t* b)
{
    asm volatile(
        "mma.sync.aligned.m16n8k16.row.col.f32.f16.f16.f32 "
        "{%0,%1,%2,%3}, {%4,%5,%6,%7}, {%8,%9}, {%0,%1,%2,%3};"
        : "+f"(d[0]), "+f"(d[1]), "+f"(d[2]), "+f"(d[3])
        : "r"(a[0]), "r"(a[1]), "r"(a[2]), "r"(a[3]), "r"(b[0]), "r"(b[1]));
}

// ===========================================================================
// fp32 -> (hi, lo) fp16 split elementwise.  dst_sel 0 = x (hi only; also
// zeroes g_ksum), 1..4 = Wq/Wk/Wv/Wo (hi+lo).
// ===========================================================================
__global__ void cvt_kernel(const float* __restrict__ src, int dst_sel, int n4)
{
    const int i = blockIdx.x * blockDim.x + threadIdx.x;
    if (i >= n4) return;
    float4 v = ((const float4*)src)[i];
    __half2 h0 = __floats2half2_rn(v.x, v.y);
    __half2 h1 = __floats2half2_rn(v.z, v.w);
    if (dst_sel == 0) {
        if (i < BHq*DHq) g_ksum[i] = 0.f;   // fold accumulator zeroing
        ((__half2*)g_xh)[i*2]   = h0;
        ((__half2*)g_xh)[i*2+1] = h1;
        return;
    }
    __half* hi = g_wh + (size_t)(dst_sel - 1) * Cq * Cq;
    __half* lo = g_wl + (size_t)(dst_sel - 1) * Cq * Cq;
    float2  b0 = __half22float2(h0);
    __half2 l0 = __floats2half2_rn(v.x - b0.x, v.y - b0.y);
    float2  b1 = __half22float2(h1);
    __half2 l1 = __floats2half2_rn(v.z - b1.x, v.w - b1.y);
    ((__half2*)hi)[i*2]   = h0;  ((__half2*)hi)[i*2+1] = h1;
    ((__half2*)lo)[i*2]   = l0;  ((__half2*)lo)[i*2+1] = l1;
}

#define SMEM_BIG     131072               // 4 stages x 32KB
#define GEMM_SMEM    98304                // 3 stages x 32KB (small core)
#define TPITCH       136

// ===========================================================================
// BIG core: 256x128 CTA, 512 threads (16 warps, 4m x 4n), BK=32, 2-product.
// 4-stage cp.async pipeline (prefetch distance 3).
// EPI: 0 = fp32 out; 1 = featmap -> q hi/lo [bh][t][d];
//      2 = (act?) -> transpose -> hi/lo [bh][d][t]; do_ks: ksum atomics (K only)
// ===========================================================================
template<int EPI>
__device__ __forceinline__ void mma_big(
    const __half* __restrict__ Ah_g,
    const __half* __restrict__ Bh_g, const __half* __restrict__ Bl_g,
    int lda, int ldb, int bmG, int bn, int bh,
    float* __restrict__ out_f32, __half* __restrict__ outh,
    __half* __restrict__ outl, bool act, bool do_ks)
{
    extern __shared__ char sm2[];
    const uint32_t sb = smem_u32(sm2);
    const int tid = threadIdx.x;

    const int rowG = tid >> 1;
    const int seg0 = (tid & 1) * 2;
    const uint32_t xrg = ((rowG >> 1) & 3) << 4;
    const uint32_t d0 = rowG*64 + (( seg0   *16) ^ xrg);
    const uint32_t d1 = rowG*64 + (((seg0+1)*16) ^ xrg);
    const __half* sA = Ah_g + (size_t)(bmG + rowG) * lda + seg0*8;
    const __half* sB = (rowG < 128)
        ? Bh_g + (size_t)(bn + rowG)       * ldb + seg0*8
        : Bl_g + (size_t)(bn + rowG - 128) * ldb + seg0*8;

    auto issue = [&](int kc, int slot) {
        const uint32_t b = sb + slot * 32768u;
        const int ko = kc * 32;
        cpa16(b          + d0, sA + ko);  cpa16(b          + d1, sA + ko + 8);
        cpa16(b + 16384u + d0, sB + ko);  cpa16(b + 16384u + d1, sB + ko + 8);
        asm volatile("cp.async.commit_group;" ::: "memory");
    };

    issue(0, 0);
    issue(1, 1);
    issue(2, 2);

    const int wid  = tid >> 5;
    const int lane = tid & 31;
    const int wm = (wid & 3) * 64;
    const int wn = (wid >> 2) * 32;
    const uint32_t xs  = ((lane >> 1) & 3) << 4;
    const uint32_t kqa = (lane >> 4) * 16;
    const uint32_t kqb = ((lane >> 3) & 1) * 16;
    uint32_t saofs[4], sbofs[2];
    #pragma unroll
    for (int mt = 0; mt < 4; mt++)
        saofs[mt] = (uint32_t)(wm + mt*16 + (lane & 15)) * 64;
    #pragma unroll
    for (int p = 0; p < 2; p++)
        sbofs[p] = (uint32_t)(wn + p*16 + ((lane >> 4) & 1)*8 + (lane & 7)) * 64;

    float acc[4][4][4];
    #pragma unroll
    for (int i = 0; i < 4; i++)
        #pragma unroll
        for (int j = 0; j < 4; j++)
            #pragma unroll
            for (int e = 0; e < 4; e++) acc[i][j][e] = 0.f;

    const int NCHUNK = Cq / 32;   // 64

    for (int kc = 0; kc < NCHUNK; kc++) {
        if (kc <= NCHUNK - 3)      asm volatile("cp.async.wait_group 2;" ::: "memory");
        else if (kc == NCHUNK - 2) asm volatile("cp.async.wait_group 1;" ::: "memory");
        else                       asm volatile("cp.async.wait_group 0;" ::: "memory");
        __syncthreads();
        if (kc + 3 < NCHUNK) issue(kc + 3, (kc + 3) & 3);

        const uint32_t st = sb + (kc & 3) * 32768u;
        #pragma unroll
        for (int ks = 0; ks < 2; ks++) {
            uint32_t ah[4][4];
            const uint32_t ca = (ks*32 + kqa) ^ xs;
            #pragma unroll
            for (int mt = 0; mt < 4; mt++)
                LDSM4(ah[mt], st + saofs[mt] + ca);
            const uint32_t cb = (ks*32 + kqb) ^ xs;
            #pragma unroll
            for (int p = 0; p < 2; p++) {
                uint32_t bh2[4], bl2[4];
                LDSM4(bh2, st + 16384u + sbofs[p] + cb);
                LDSM4(bl2, st + 24576u + sbofs[p] + cb);
                #pragma unroll
                for (int mt = 0; mt < 4; mt++) {
                    mma16816(acc[mt][2*p],   ah[mt], bh2);
                    mma16816(acc[mt][2*p],   ah[mt], bl2);
                    mma16816(acc[mt][2*p+1], ah[mt], bh2 + 2);
                    mma16816(acc[mt][2*p+1], ah[mt], bl2 + 2);
                }
            }
        }
    }

    const int r0 = lane >> 2;
    const int c0 = (lane & 3) * 2;

    if constexpr (EPI == 2) {
        __syncthreads();
        __half* shh = (__half*)sm2;
        __half* shl = shh + 128*TPITCH;
        const int myhh = (wid & 3) >> 1;
        const int dd = tid >> 2;
        const int ts = (tid & 3) * 32;
        float ksacc = 0.f;
        #pragma unroll
        for (int hh = 0; hh < 2; hh++) {
            if (myhh == hh) {
                #pragma unroll
                for (int mt = 0; mt < 4; mt++)
                    #pragma unroll
                    for (int half = 0; half < 2; half++) {
                        const int lt = (wm + mt*16 + r0 + half*8) & 127;
                        #pragma unroll
                        for (int nt = 0; nt < 4; nt++) {
                            const int n0 = wn + nt*8 + c0;
                            float v0 = acc[mt][nt][half*2];
                            float v1 = acc[mt][nt][half*2 + 1];
                            if (act) { v0 = featmap(v0); v1 = featmap(v1); }
                            __half h0 = __float2half_rn(v0);
                            __half h1 = __float2half_rn(v1);
                            __half l0 = __float2half_rn(v0 - __half2float(h0));
                            __half l1 = __float2half_rn(v1 - __half2float(h1));
                            shh[ n0   *TPITCH + lt] = h0;
                            shh[(n0+1)*TPITCH + lt] = h1;
                            shl[ n0   *TPITCH + lt] = l0;
                            shl[(n0+1)*TPITCH + lt] = l1;
                        }
                    }
            }
            __syncthreads();
            const int tdst = (bmG & (Tq - 1)) + hh*128 + ts;
            const uint4* srcH = (const uint4*)(shh + dd*TPITCH + ts);
            const uint4* srcL = (const uint4*)(shl + dd*TPITCH + ts);
            uint4* dstH = (uint4*)(outh + ((size_t)bh*DHq + dd)*Tq + tdst);
            uint4* dstL = (uint4*)(outl + ((size_t)bh*DHq + dd)*Tq + tdst);
            #pragma unroll
            for (int q = 0; q < 4; q++) {
                uint4 h4 = srcH[q], l4 = srcL[q];
                dstH[q] = h4; dstL[q] = l4;
                if (do_ks) {
                    const __half2* hp = (const __half2*)&h4;
                    const __half2* lp = (const __half2*)&l4;
                    #pragma unroll
                    for (int e = 0; e < 4; e++) {
                        float2 a = __half22float2(hp[e]);
                        float2 b = __half22float2(lp[e]);
                        ksacc += a.x + a.y + b.x + b.y;
                    }
                }
            }
            __syncthreads();
        }
        if (do_ks) atomicAdd(&g_ksum[bh*DHq + dd], ksacc);
        return;
    }

    #pragma unroll
    for (int mt = 0; mt < 4; mt++) {
        #pragma unroll
        for (int half = 0; half < 2; half++) {
            const int lm = wm + mt*16 + r0 + half*8;
            #pragma unroll
            for (int nt = 0; nt < 4; nt++) {
                const int n0 = wn + nt*8 + c0;
                float v0 = acc[mt][nt][half*2];
                float v1 = acc[mt][nt][half*2 + 1];
                if constexpr (EPI == 0) {
                    float* op = out_f32 + (size_t)(bmG + lm) * Cq + bn;
                    *(float2*)(op + n0) = make_float2(v0, v1);
                } else if constexpr (EPI == 1) {
                    if (act) { v0 = featmap(v0); v1 = featmap(v1); }
                    const int t = (bmG + lm) & (Tq - 1);
                    const size_t base = ((size_t)bh*Tq + t)*DHq;
                    __half2 h2 = __floats2half2_rn(v0, v1);
                    float2  bk = __half22float2(h2);
                    __half2 l2 = __floats2half2_rn(v0 - bk.x, v1 - bk.y);
                    *(__half2*)&outh[base + n0] = h2;
                    *(__half2*)&outl[base + n0] = l2;
                }
            }
        }
    }
}

// ===========================================================================
// Small 128x128 3-product core.
// EPI 4 = attn (z computed in-kernel from ksum), EPI 5 = kv fp32 partial.
// ===========================================================================
template<int EPI>
__device__ __forceinline__ void mma_core(
    const __half* __restrict__ Ah_g, const __half* __restrict__ Al_g,
    const __half* __restrict__ Bh_g, const __half* __restrict__ Bl_g,
    int lda, int ldb, int Klen, int koff, int bm, int bn, int bh,
    float* __restrict__ out_f32, __half* __restrict__ outh,
    const float* __restrict__ kss)
{
    extern __shared__ char sm2[];
    const uint32_t sb = smem_u32(sm2);
    const int tid = threadIdx.x;

    const int rowG = tid >> 1;
    const int seg0 = (tid & 1) * 2;
    const uint32_t xrg = ((rowG >> 1) & 3) << 4;
    const uint32_t d0 = rowG*64 + (( seg0   *16) ^ xrg);
    const uint32_t d1 = rowG*64 + (((seg0+1)*16) ^ xrg);
    const __half* sAh = Ah_g + (size_t)(bm + rowG) * lda + seg0*8 + koff;
    const __half* sAl = Al_g + (size_t)(bm + rowG) * lda + seg0*8 + koff;
    const __half* sBh = Bh_g + (size_t)(bn + rowG) * ldb + seg0*8 + koff;
    const __half* sBl = Bl_g + (size_t)(bn + rowG) * ldb + seg0*8 + koff;

    auto issue = [&](int kc, int slot) {
        const uint32_t b = sb + slot * 32768u;
        const int ko = kc * 32;
        cpa16(b          + d0, sAh + ko);  cpa16(b          + d1, sAh + ko + 8);
        cpa16(b +  8192u + d0, sAl + ko);  cpa16(b +  8192u + d1, sAl + ko + 8);
        cpa16(b + 16384u + d0, sBh + ko);  cpa16(b + 16384u + d1, sBh + ko + 8);
        cpa16(b + 24576u + d0, sBl + ko);  cpa16(b + 24576u + d1, sBl + ko + 8);
        asm volatile("cp.async.commit_group;" ::: "memory");
    };

    issue(0, 0);
    issue(1, 1);

    const int wid  = tid >> 5;
    const int lane = tid & 31;
    const int wm = (wid & 3) * 32;
    const int wn = (wid >> 2) * 64;
    const uint32_t xs  = ((lane >> 1) & 3) << 4;
    const uint32_t kqa = (lane >> 4) * 16;
    const uint32_t kqb = ((lane >> 3) & 1) * 16;
    uint32_t saofs[2], sbofs[4];
    #pragma unroll
    for (int mt = 0; mt < 2; mt++)
        saofs[mt] = (uint32_t)(wm + mt*16 + (lane & 15)) * 64;
    #pragma unroll
    for (int p = 0; p < 4; p++)
        sbofs[p] = (uint32_t)(wn + p*16 + ((lane >> 4) & 1)*8 + (lane & 7)) * 64;

    float acc[2][8][4];
    #pragma unroll
    for (int i = 0; i < 2; i++)
        #pragma unroll
        for (int j = 0; j < 8; j++)
            #pragma unroll
            for (int e = 0; e < 4; e++) acc[i][j][e] = 0.f;

    const int NCHUNK = Klen / 32;

    for (int kc = 0; kc < NCHUNK; kc++) {
        if (kc == NCHUNK - 1) asm volatile("cp.async.wait_group 0;" ::: "memory");
        else                  asm volatile("cp.async.wait_group 1;" ::: "memory");
        __syncthreads();
        if (kc + 2 < NCHUNK) issue(kc + 2, (kc + 2) % 3);

        const uint32_t st = sb + (kc % 3) * 32768u;
        #pragma unroll
        for (int ks = 0; ks < 2; ks++) {
            uint32_t ah[2][4], al[2][4];
            const uint32_t ca = (ks*32 + kqa) ^ xs;
            #pragma unroll
            for (int mt = 0; mt < 2; mt++) {
                LDSM4(ah[mt], st + saofs[mt] + ca);
                LDSM4(al[mt], st + 8192u + saofs[mt] + ca);
            }
            const uint32_t cb = (ks*32 + kqb) ^ xs;
            #pragma unroll
            for (int p = 0; p < 4; p++) {
                uint32_t bh2[4], bl2[4];
                LDSM4(bh2, st + 16384u + sbofs[p] + cb);
                LDSM4(bl2, st + 24576u + sbofs[p] + cb);
                #pragma unroll
                for (int mt = 0; mt < 2; mt++) {
                    mma16816(acc[mt][2*p],   ah[mt], bh2);
                    mma16816(acc[mt][2*p],   ah[mt], bl2);
                    mma16816(acc[mt][2*p],   al[mt], bh2);
                    mma16816(acc[mt][2*p+1], ah[mt], bh2 + 2);
                    mma16816(acc[mt][2*p+1], ah[mt], bl2 + 2);
                    mma16816(acc[mt][2*p+1], al[mt], bh2 + 2);
                }
            }
        }
    }

    const int r0 = lane >> 2;
    const int c0 = (lane & 3) * 2;

    if constexpr (EPI == 4) {
        // z-phase: zs[t] = 1/(q[t]·ksum + 1e-6)
        __syncthreads();
        float* zs = (float*)sm2;
        if (tid < 128) {
            const __half2* qh2 = (const __half2*)(Ah_g + (size_t)(bm + tid)*lda);
            const __half2* ql2 = (const __half2*)(Al_g + (size_t)(bm + tid)*lda);
            const float2* kf = (const float2*)kss;
            float s = 0.f;
            #pragma unroll 16
            for (int i = 0; i < 64; i++) {
                float2 a = __half22float2(qh2[i]);
                float2 b = __half22float2(ql2[i]);
                float2 k2 = kf[i];
                s += (a.x + b.x) * k2.x + (a.y + b.y) * k2.y;
            }
            zs[tid] = 1.f / (s + 1e-6f);
        }
        __syncthreads();
        #pragma unroll
        for (int mt = 0; mt < 2; mt++)
            #pragma unroll
            for (int half = 0; half < 2; half++) {
                const int lm = wm + mt*16 + r0 + half*8;
                const float z = zs[lm];
                const int t = bm + lm;
                const size_t base =
                    ((size_t)(bh >> 4)*Tq + t)*Cq + (size_t)(bh & 15)*DHq;
                #pragma unroll
                for (int nt = 0; nt < 8; nt++) {
                    const int n0 = wn + nt*8 + c0;
                    *(__half2*)&outh[base + n0] =
                        __floats2half2_rn(acc[mt][nt][half*2] * z,
                                          acc[mt][nt][half*2 + 1] * z);
                }
            }
        return;
    }

    // EPI == 5: fp32 partial, pitch DHq
    #pragma unroll
    for (int mt = 0; mt < 2; mt++)
        #pragma unroll
        for (int half = 0; half < 2; half++) {
            const int lm = wm + mt*16 + r0 + half*8;
            #pragma unroll
            for (int nt = 0; nt < 8; nt++) {
                const int n0 = wn + nt*8 + c0;
                *(float2*)(out_f32 + (size_t)lm*DHq + n0) =
                    make_float2(acc[mt][nt][half*2], acc[mt][nt][half*2 + 1]);
            }
        }
}

// ---------------------------------------------------------------------------
// kernels
// ---------------------------------------------------------------------------
__global__ __launch_bounds__(512, 1)
void qkv_mma_kernel()
{
    const int h   = blockIdx.x;
    const int bmG = blockIdx.y * 256;
    const int z   = blockIdx.z;
    const int bh  = ((bmG >> 12) << 4) + h;
    const __half* Wh = g_wh + (size_t)z * Cq * Cq;
    const __half* Wl = g_wl + (size_t)z * Cq * Cq;
    if (z == 0)
        mma_big<1>(g_xh, Wh, Wl, Cq, Cq, bmG, h*128, bh,
                   nullptr, g_qh, g_ql, true, false);
    else if (z == 1)
        mma_big<2>(g_xh, Wh, Wl, Cq, Cq, bmG, h*128, bh,
                   nullptr, g_kth, g_ktl, true, true);
    else
        mma_big<2>(g_xh, Wh, Wl, Cq, Cq, bmG, h*128, bh,
                   nullptr, g_vth, g_vtl, false, false);
}

__global__ __launch_bounds__(512, 1)
void out_mma_kernel(float* __restrict__ out)
{
    mma_big<0>(g_ath, g_wh + (size_t)3*Cq*Cq, g_wl + (size_t)3*Cq*Cq,
               Cq, Cq, blockIdx.y*256, blockIdx.x*128, 0,
               out, nullptr, nullptr, false, false);
}

__global__ __launch_bounds__(256, 2)
void kv_part_kernel()
{
    const int bh = blockIdx.x;
    const int p  = blockIdx.y;
    const size_t o = (size_t)bh * DHq * Tq;
    float* outp = g_kvp + ((size_t)p*BHq + bh) * DHq * DHq;
    mma_core<5>(g_vth + o, g_vtl + o, g_kth + o, g_ktl + o,
                Tq, Tq, 1024, p*1024, 0, 0, bh, outp, nullptr, nullptr);
}

__global__ void kv_reduce_kernel()
{
    const int i = blockIdx.x * blockDim.x + threadIdx.x;   // pair index
    const int base = i * 2;
    float s0 = 0.f, s1 = 0.f;
    #pragma unroll
    for (int p = 0; p < 4; p++) {
        const float2 v = *(const float2*)&g_kvp[(size_t)p*BHq*DHq*DHq + base];
        s0 += v.x; s1 += v.y;
    }
    __half2 h2 = __floats2half2_rn(s0, s1);
    float2  bk = __half22float2(h2);
    __half2 l2 = __floats2half2_rn(s0 - bk.x, s1 - bk.y);
    *(__half2*)&g_kvh[base] = h2;
    *(__half2*)&g_kvl[base] = l2;
}

__global__ __launch_bounds__(256, 2)
void attn_mma_kernel()
{
    const int bh = blockIdx.x;
    const int bm = blockIdx.y * 128;
    const size_t oq = (size_t)bh * Tq * DHq;
    const size_t ok = (size_t)bh * DHq * DHq;
    mma_core<4>(g_qh + oq, g_ql + oq, g_kvh + ok, g_kvl + ok,
                DHq, DHq, DHq, 0, bm, 0, bh,
                nullptr, g_ath, g_ksum + bh*DHq);
}

// ---------------------------------------------------------------------------
extern "C" void kernel_launch(void* const* d_in, const int* in_sizes, int n_in,
                              void* d_out, int out_size)
{
    const float* x  = (const float*)d_in[0];
    // d_in[1] = cos, d_in[2] = sin : unused by the reference module
    const float* Wq = (const float*)d_in[3];
    const float* Wk = (const float*)d_in[4];
    const float* Wv = (const float*)d_in[5];
    const float* Wo = (const float*)d_in[6];
    float* out = (float*)d_out;

    cudaFuncSetAttribute(qkv_mma_kernel,
                         cudaFuncAttributeMaxDynamicSharedMemorySize, SMEM_BIG);
    cudaFuncSetAttribute(out_mma_kernel,
                         cudaFuncAttributeMaxDynamicSharedMemorySize, SMEM_BIG);
    cudaFuncSetAttribute(kv_part_kernel,
                         cudaFuncAttributeMaxDynamicSharedMemorySize, GEMM_SMEM);
    cudaFuncSetAttribute(attn_mma_kernel,
                         cudaFuncAttributeMaxDynamicSharedMemorySize, GEMM_SMEM);

    // Launch order chosen so qkv_mma is the 5th launch (ncu captures it):
    // cvt_x (also zeroes ksum), Wq, Wk, Wv, then qkv.  Wo's cvt is only
    // needed by out_mma and moves after qkv.
    cvt_kernel<<<(Mq*Cq/4 + 255)/256, 256>>>(x,  0, Mq*Cq/4);
    cvt_kernel<<<(Cq*Cq/4 + 255)/256, 256>>>(Wq, 1, Cq*Cq/4);
    cvt_kernel<<<(Cq*Cq/4 + 255)/256, 256>>>(Wk, 2, Cq*Cq/4);
    cvt_kernel<<<(Cq*Cq/4 + 255)/256, 256>>>(Wv, 3, Cq*Cq/4);

    qkv_mma_kernel<<<dim3(Hq, Mq/256, 3), 512, SMEM_BIG>>>();

    cvt_kernel<<<(Cq*Cq/4 + 255)/256, 256>>>(Wo, 4, Cq*Cq/4);
    kv_part_kernel<<<dim3(BHq, 4), 256, GEMM_SMEM>>>();
    kv_reduce_kernel<<<BHq*DHq*DHq/2/256, 256>>>();
    attn_mma_kernel<<<dim3(BHq, Tq/128), 256, GEMM_SMEM>>>();
    out_mma_kernel<<<dim3(Cq/128, Mq/256), 512, SMEM_BIG>>>(out);
}

// round 16
// speedup vs baseline: 1.1147x; 1.1123x over previous
#include <cuda_runtime.h>
#include <cuda_fp16.h>
#include <cstdint>

// Problem constants
#define Bq   4
#define Tq   4096
#define Cq   2048
#define Hq   16
#define DHq  128
#define Mq   (Bq*Tq)          // 16384
#define BHq  (Bq*Hq)          // 64

// -------- device globals (allocation-free rule) --------
__device__ __half g_xh[Mq*Cq];     // x hi [m][c]
__device__ __half g_wh[4*Cq*Cq];   // Wq|Wk|Wv|Wo hi [o][c]
__device__ __half g_wl[4*Cq*Cq];   // lo (Wo lo unused now, kept for layout)
__device__ __half g_qh[Mq*Cq];     // q hi/lo [bh][t][d]
__device__ __half g_ql[Mq*Cq];
__device__ __half g_kth[Mq*Cq];    // kT hi/lo [bh][d][t]
__device__ __half g_ktl[Mq*Cq];
__device__ __half g_vth[Mq*Cq];    // vT hi/lo [bh][d][t]
__device__ __half g_vtl[Mq*Cq];
__device__ float  g_kvp[4*BHq*DHq*DHq];  // kv split-T fp32 partials
__device__ __half g_kvh[BHq*DHq*DHq];    // kvT[e][d] hi/lo
__device__ __half g_kvl[BHq*DHq*DHq];
__device__ __half g_ath[Mq*Cq];    // attention out hi [b,t,C]
__device__ float  g_ksum[BHq*DHq];

__device__ __forceinline__ float featmap(float y) {
    return y > 0.f ? y + 1.f : __expf(y);   // elu(y)+1
}

__device__ __forceinline__ uint32_t smem_u32(const void* p) {
    uint32_t a;
    asm("{ .reg .u64 t; cvta.to.shared.u64 t, %1; cvt.u32.u64 %0, t; }"
        : "=r"(a) : "l"(p));
    return a;
}

__device__ __forceinline__ void cpa16(uint32_t s, const void* g) {
    asm volatile("cp.async.cg.shared.global [%0], [%1], 16;" :: "r"(s), "l"(g));
}

#define LDSM4(r, a)                                                            \
    asm volatile("ldmatrix.sync.aligned.m8n8.x4.shared.b16 {%0,%1,%2,%3}, [%4];" \
        : "=r"((r)[0]), "=r"((r)[1]), "=r"((r)[2]), "=r"((r)[3]) : "r"(a))

__device__ __forceinline__ void mma16816(float* d, const uint32_t* a, const uint32_t* b)
{
    asm volatile(
        "mma.sync.aligned.m16n8k16.row.col.f32.f16.f16.f32 "
        "{%0,%1,%2,%3}, {%4,%5,%6,%7}, {%8,%9}, {%0,%1,%2,%3};"
        : "+f"(d[0]), "+f"(d[1]), "+f"(d[2]), "+f"(d[3])
        : "r"(a[0]), "r"(a[1]), "r"(a[2]), "r"(a[3]), "r"(b[0]), "r"(b[1]));
}

__device__ __forceinline__ void cvt_store_w(const float* __restrict__ src,
                                            __half* hi, __half* lo, int i)
{
    float4 v = ((const float4*)src)[i];
    __half2 h0 = __floats2half2_rn(v.x, v.y);
    __half2 h1 = __floats2half2_rn(v.z, v.w);
    float2  b0 = __half22float2(h0);
    __half2 l0 = __floats2half2_rn(v.x - b0.x, v.y - b0.y);
    float2  b1 = __half22float2(h1);
    __half2 l1 = __floats2half2_rn(v.z - b1.x, v.w - b1.y);
    ((__half2*)hi)[i*2]   = h0;  ((__half2*)hi)[i*2+1] = h1;
    ((__half2*)lo)[i*2]   = l0;  ((__half2*)lo)[i*2+1] = l1;
}

// ===========================================================================
// cvt_all: one launch for x (hi only, + ksum zero) and Wq/Wk/Wv (hi+lo).
// ===========================================================================
#define NXB  (Mq*Cq/4/256)   // 32768
#define NWB  (Cq*Cq/4/256)   // 4096

__global__ void cvt_all_kernel(const float* __restrict__ x,
                               const float* __restrict__ Wq,
                               const float* __restrict__ Wk,
                               const float* __restrict__ Wv)
{
    const int blk = blockIdx.x;
    if (blk < NXB) {
        const int i = blk * 256 + threadIdx.x;
        if (i < BHq*DHq) g_ksum[i] = 0.f;
        float4 v = ((const float4*)x)[i];
        ((__half2*)g_xh)[i*2]   = __floats2half2_rn(v.x, v.y);
        ((__half2*)g_xh)[i*2+1] = __floats2half2_rn(v.z, v.w);
        return;
    }
    const int s = (blk - NXB) / NWB;          // 0..2
    const int i = ((blk - NXB) - s*NWB) * 256 + threadIdx.x;
    const float* src = (s == 0) ? Wq : (s == 1) ? Wk : Wv;
    cvt_store_w(src, g_wh + (size_t)s*Cq*Cq, g_wl + (size_t)s*Cq*Cq, i);
}

#define SMEM_BIG2    131072               // big core NPROD2: 4 x 32KB
#define SMEM_STD     98304                // big NPROD1 (4x24KB) / small cores
#define TPITCH       136

// ===========================================================================
// BIG core: 256x128 CTA, 512 threads (16 warps, 4m x 4n), BK=32.
// NPROD=2: B hi+lo (stage 32KB); NPROD=1: B hi (24KB). 4 slots, depth 3.
// EPI: 0 = fp32 out; 2 = (act?) -> transpose -> hi/lo [bh][d][t] (+ksum atomics)
// ===========================================================================
template<int EPI, int NPROD>
__device__ __forceinline__ void mma_big(
    const __half* __restrict__ Ah_g,
    const __half* __restrict__ Bh_g, const __half* __restrict__ Bl_g,
    int lda, int ldb, int bmG, int bn, int bh,
    float* __restrict__ out_f32, __half* __restrict__ outh,
    __half* __restrict__ outl, bool act, bool do_ks)
{
    constexpr uint32_t STG = (NPROD == 2) ? 32768u : 24576u;

    extern __shared__ char sm2[];
    const uint32_t sb = smem_u32(sm2);
    const int tid = threadIdx.x;

    const int rowG = tid >> 1;
    const int seg0 = (tid & 1) * 2;
    const uint32_t xrg = ((rowG >> 1) & 3) << 4;
    const uint32_t d0 = rowG*64 + (( seg0   *16) ^ xrg);
    const uint32_t d1 = rowG*64 + (((seg0+1)*16) ^ xrg);
    const __half* sA = Ah_g + (size_t)(bmG + rowG) * lda + seg0*8;
    const __half* sB = (rowG < 128)
        ? Bh_g + (size_t)(bn + rowG)       * ldb + seg0*8
        : Bl_g + (size_t)(bn + rowG - 128) * ldb + seg0*8;
    const bool loadB = (NPROD == 2) || (rowG < 128);

    auto issue = [&](int kc, int slot) {
        const uint32_t b = sb + slot * STG;
        const int ko = kc * 32;
        cpa16(b          + d0, sA + ko);  cpa16(b          + d1, sA + ko + 8);
        if (loadB) {
            cpa16(b + 16384u + d0, sB + ko);  cpa16(b + 16384u + d1, sB + ko + 8);
        }
        asm volatile("cp.async.commit_group;" ::: "memory");
    };

    issue(0, 0);
    issue(1, 1);
    issue(2, 2);

    const int wid  = tid >> 5;
    const int lane = tid & 31;
    const int wm = (wid & 3) * 64;
    const int wn = (wid >> 2) * 32;
    const uint32_t xs  = ((lane >> 1) & 3) << 4;
    const uint32_t kqa = (lane >> 4) * 16;
    const uint32_t kqb = ((lane >> 3) & 1) * 16;
    uint32_t saofs[4], sbofs[2];
    #pragma unroll
    for (int mt = 0; mt < 4; mt++)
        saofs[mt] = (uint32_t)(wm + mt*16 + (lane & 15)) * 64;
    #pragma unroll
    for (int p = 0; p < 2; p++)
        sbofs[p] = (uint32_t)(wn + p*16 + ((lane >> 4) & 1)*8 + (lane & 7)) * 64;

    float acc[4][4][4];
    #pragma unroll
    for (int i = 0; i < 4; i++)
        #pragma unroll
        for (int j = 0; j < 4; j++)
            #pragma unroll
            for (int e = 0; e < 4; e++) acc[i][j][e] = 0.f;

    const int NCHUNK = Cq / 32;   // 64

    for (int kc = 0; kc < NCHUNK; kc++) {
        if (kc <= NCHUNK - 3)      asm volatile("cp.async.wait_group 2;" ::: "memory");
        else if (kc == NCHUNK - 2) asm volatile("cp.async.wait_group 1;" ::: "memory");
        else                       asm volatile("cp.async.wait_group 0;" ::: "memory");
        __syncthreads();
        if (kc + 3 < NCHUNK) issue(kc + 3, (kc + 3) & 3);

        const uint32_t st = sb + (kc & 3) * STG;
        #pragma unroll
        for (int ks = 0; ks < 2; ks++) {
            uint32_t ah[4][4];
            const uint32_t ca = (ks*32 + kqa) ^ xs;
            #pragma unroll
            for (int mt = 0; mt < 4; mt++)
                LDSM4(ah[mt], st + saofs[mt] + ca);
            const uint32_t cb = (ks*32 + kqb) ^ xs;
            #pragma unroll
            for (int p = 0; p < 2; p++) {
                uint32_t bh2[4];
                LDSM4(bh2, st + 16384u + sbofs[p] + cb);
                if (NPROD == 2) {
                    uint32_t bl2[4];
                    LDSM4(bl2, st + 24576u + sbofs[p] + cb);
                    #pragma unroll
                    for (int mt = 0; mt < 4; mt++) {
                        mma16816(acc[mt][2*p],   ah[mt], bh2);
                        mma16816(acc[mt][2*p],   ah[mt], bl2);
                        mma16816(acc[mt][2*p+1], ah[mt], bh2 + 2);
                        mma16816(acc[mt][2*p+1], ah[mt], bl2 + 2);
                    }
                } else {
                    #pragma unroll
                    for (int mt = 0; mt < 4; mt++) {
                        mma16816(acc[mt][2*p],   ah[mt], bh2);
                        mma16816(acc[mt][2*p+1], ah[mt], bh2 + 2);
                    }
                }
            }
        }
    }

    const int r0 = lane >> 2;
    const int c0 = (lane & 3) * 2;

    if constexpr (EPI == 2) {
        __syncthreads();
        __half* shh = (__half*)sm2;
        __half* shl = shh + 128*TPITCH;
        const int myhh = (wid & 3) >> 1;
        const int dd = tid >> 2;
        const int ts = (tid & 3) * 32;
        float ksacc = 0.f;
        #pragma unroll
        for (int hh = 0; hh < 2; hh++) {
            if (myhh == hh) {
                #pragma unroll
                for (int mt = 0; mt < 4; mt++)
                    #pragma unroll
                    for (int half = 0; half < 2; half++) {
                        const int lt = (wm + mt*16 + r0 + half*8) & 127;
                        #pragma unroll
                        for (int nt = 0; nt < 4; nt++) {
                            const int n0 = wn + nt*8 + c0;
                            float v0 = acc[mt][nt][half*2];
                            float v1 = acc[mt][nt][half*2 + 1];
                            if (act) { v0 = featmap(v0); v1 = featmap(v1); }
                            __half h0 = __float2half_rn(v0);
                            __half h1 = __float2half_rn(v1);
                            __half l0 = __float2half_rn(v0 - __half2float(h0));
                            __half l1 = __float2half_rn(v1 - __half2float(h1));
                            shh[ n0   *TPITCH + lt] = h0;
                            shh[(n0+1)*TPITCH + lt] = h1;
                            shl[ n0   *TPITCH + lt] = l0;
                            shl[(n0+1)*TPITCH + lt] = l1;
                        }
                    }
            }
            __syncthreads();
            const int tdst = (bmG & (Tq - 1)) + hh*128 + ts;
            const uint4* srcH = (const uint4*)(shh + dd*TPITCH + ts);
            const uint4* srcL = (const uint4*)(shl + dd*TPITCH + ts);
            uint4* dstH = (uint4*)(outh + ((size_t)bh*DHq + dd)*Tq + tdst);
            uint4* dstL = (uint4*)(outl + ((size_t)bh*DHq + dd)*Tq + tdst);
            #pragma unroll
            for (int q = 0; q < 4; q++) {
                uint4 h4 = srcH[q], l4 = srcL[q];
                dstH[q] = h4; dstL[q] = l4;
                if (do_ks) {
                    const __half2* hp = (const __half2*)&h4;
                    const __half2* lp = (const __half2*)&l4;
                    #pragma unroll
                    for (int e = 0; e < 4; e++) {
                        float2 a = __half22float2(hp[e]);
                        float2 b = __half22float2(lp[e]);
                        ksacc += a.x + a.y + b.x + b.y;
                    }
                }
            }
            __syncthreads();
        }
        if (do_ks) atomicAdd(&g_ksum[bh*DHq + dd], ksacc);
        return;
    }

    // EPI == 0
    #pragma unroll
    for (int mt = 0; mt < 4; mt++)
        #pragma unroll
        for (int half = 0; half < 2; half++) {
            const int lm = wm + mt*16 + r0 + half*8;
            #pragma unroll
            for (int nt = 0; nt < 4; nt++) {
                const int n0 = wn + nt*8 + c0;
                float* op = out_f32 + (size_t)(bmG + lm) * Cq + bn;
                *(float2*)(op + n0) =
                    make_float2(acc[mt][nt][half*2], acc[mt][nt][half*2 + 1]);
            }
        }
}

// ===========================================================================
// Small 128x128 core, 256 threads (8 warps, 4m x 2n).
// NPROD=2: A hi; B hi+lo (24KB stage, 4 slots, depth 3).
// NPROD=3: A hi+lo; B hi+lo (32KB stage, 3 slots, depth 2).
// EPI: 1 = featmap -> q hi/lo; 4 = attn (z in-kernel); 5 = kv fp32 partial.
// ===========================================================================
template<int EPI, int NPROD>
__device__ __forceinline__ void mma_small(
    const __half* __restrict__ Ah_g, const __half* __restrict__ Al_g,
    const __half* __restrict__ Bh_g, const __half* __restrict__ Bl_g,
    int lda, int ldb, int Klen, int koff, int bm, int bn, int bh,
    float* __restrict__ out_f32, __half* __restrict__ outh,
    __half* __restrict__ outl, const float* __restrict__ kss, bool act)
{
    constexpr uint32_t STG  = (NPROD == 2) ? 24576u : 32768u;
    constexpr int      NSTG = (NPROD == 2) ? 4 : 3;
    constexpr uint32_t OBH  = (NPROD == 2) ? 8192u  : 16384u;
    constexpr uint32_t OBL  = OBH + 8192u;

    extern __shared__ char sm2[];
    const uint32_t sb = smem_u32(sm2);
    const int tid = threadIdx.x;

    const int rowG = tid >> 1;
    const int seg0 = (tid & 1) * 2;
    const uint32_t xrg = ((rowG >> 1) & 3) << 4;
    const uint32_t d0 = rowG*64 + (( seg0   *16) ^ xrg);
    const uint32_t d1 = rowG*64 + (((seg0+1)*16) ^ xrg);
    const __half* sAh = Ah_g + (size_t)(bm + rowG) * lda + seg0*8 + koff;
    const __half* sAl = Al_g + (size_t)(bm + rowG) * lda + seg0*8 + koff;
    const __half* sBh = Bh_g + (size_t)(bn + rowG) * ldb + seg0*8 + koff;
    const __half* sBl = Bl_g + (size_t)(bn + rowG) * ldb + seg0*8 + koff;

    auto issue = [&](int kc, int slot) {
        const uint32_t b = sb + slot * STG;
        const int ko = kc * 32;
        cpa16(b       + d0, sAh + ko);  cpa16(b       + d1, sAh + ko + 8);
        if (NPROD == 3) {
            cpa16(b + 8192u + d0, sAl + ko);  cpa16(b + 8192u + d1, sAl + ko + 8);
        }
        cpa16(b + OBH + d0, sBh + ko);  cpa16(b + OBH + d1, sBh + ko + 8);
        cpa16(b + OBL + d0, sBl + ko);  cpa16(b + OBL + d1, sBl + ko + 8);
        asm volatile("cp.async.commit_group;" ::: "memory");
    };

    const int NCHUNK = Klen / 32;

    issue(0, 0);
    issue(1, 1);
    if (NPROD == 2 && NCHUNK > 2) issue(2, 2);

    const int wid  = tid >> 5;
    const int lane = tid & 31;
    const int wm = (wid & 3) * 32;
    const int wn = (wid >> 2) * 64;
    const uint32_t xs  = ((lane >> 1) & 3) << 4;
    const uint32_t kqa = (lane >> 4) * 16;
    const uint32_t kqb = ((lane >> 3) & 1) * 16;
    uint32_t saofs[2], sbofs[4];
    #pragma unroll
    for (int mt = 0; mt < 2; mt++)
        saofs[mt] = (uint32_t)(wm + mt*16 + (lane & 15)) * 64;
    #pragma unroll
    for (int p = 0; p < 4; p++)
        sbofs[p] = (uint32_t)(wn + p*16 + ((lane >> 4) & 1)*8 + (lane & 7)) * 64;

    float acc[2][8][4];
    #pragma unroll
    for (int i = 0; i < 2; i++)
        #pragma unroll
        for (int j = 0; j < 8; j++)
            #pragma unroll
            for (int e = 0; e < 4; e++) acc[i][j][e] = 0.f;

    for (int kc = 0; kc < NCHUNK; kc++) {
        if (NPROD == 2) {
            if (kc < NCHUNK - 2)       asm volatile("cp.async.wait_group 2;" ::: "memory");
            else if (kc == NCHUNK - 2) asm volatile("cp.async.wait_group 1;" ::: "memory");
            else                       asm volatile("cp.async.wait_group 0;" ::: "memory");
        } else {
            if (kc == NCHUNK - 1) asm volatile("cp.async.wait_group 0;" ::: "memory");
            else                  asm volatile("cp.async.wait_group 1;" ::: "memory");
        }
        __syncthreads();
        if (NPROD == 2) { if (kc + 3 < NCHUNK) issue(kc + 3, (kc + 3) % NSTG); }
        else            { if (kc + 2 < NCHUNK) issue(kc + 2, (kc + 2) % NSTG); }

        const uint32_t st = sb + (kc % NSTG) * STG;
        #pragma unroll
        for (int ks = 0; ks < 2; ks++) {
            uint32_t ah[2][4], al[2][4];
            const uint32_t ca = (ks*32 + kqa) ^ xs;
            #pragma unroll
            for (int mt = 0; mt < 2; mt++) {
                LDSM4(ah[mt], st + saofs[mt] + ca);
                if (NPROD == 3) LDSM4(al[mt], st + 8192u + saofs[mt] + ca);
            }
            const uint32_t cb = (ks*32 + kqb) ^ xs;
            #pragma unroll
            for (int p = 0; p < 4; p++) {
                uint32_t bh2[4], bl2[4];
                LDSM4(bh2, st + OBH + sbofs[p] + cb);
                LDSM4(bl2, st + OBL + sbofs[p] + cb);
                #pragma unroll
                for (int mt = 0; mt < 2; mt++) {
                    mma16816(acc[mt][2*p],   ah[mt], bh2);
                    mma16816(acc[mt][2*p],   ah[mt], bl2);
                    if (NPROD == 3) mma16816(acc[mt][2*p], al[mt], bh2);
                    mma16816(acc[mt][2*p+1], ah[mt], bh2 + 2);
                    mma16816(acc[mt][2*p+1], ah[mt], bl2 + 2);
                    if (NPROD == 3) mma16816(acc[mt][2*p+1], al[mt], bh2 + 2);
                }
            }
        }
    }

    const int r0 = lane >> 2;
    const int c0 = (lane & 3) * 2;

    if constexpr (EPI == 4) {
        __syncthreads();
        float* zs = (float*)sm2;
        if (tid < 128) {
            const __half2* qh2 = (const __half2*)(Ah_g + (size_t)(bm + tid)*lda);
            const __half2* ql2 = (const __half2*)(Al_g + (size_t)(bm + tid)*lda);
            const float2* kf = (const float2*)kss;
            float s = 0.f;
            #pragma unroll 16
            for (int i = 0; i < 64; i++) {
                float2 a = __half22float2(qh2[i]);
                float2 b = __half22float2(ql2[i]);
                float2 k2 = kf[i];
                s += (a.x + b.x) * k2.x + (a.y + b.y) * k2.y;
            }
            zs[tid] = 1.f / (s + 1e-6f);
        }
        __syncthreads();
        #pragma unroll
        for (int mt = 0; mt < 2; mt++)
            #pragma unroll
            for (int half = 0; half < 2; half++) {
                const int lm = wm + mt*16 + r0 + half*8;
                const float z = zs[lm];
                const int t = bm + lm;
                const size_t base =
                    ((size_t)(bh >> 4)*Tq + t)*Cq + (size_t)(bh & 15)*DHq;
                #pragma unroll
                for (int nt = 0; nt < 8; nt++) {
                    const int n0 = wn + nt*8 + c0;
                    *(__half2*)&outh[base + n0] =
                        __floats2half2_rn(acc[mt][nt][half*2] * z,
                                          acc[mt][nt][half*2 + 1] * z);
                }
            }
        return;
    }

    #pragma unroll
    for (int mt = 0; mt < 2; mt++)
        #pragma unroll
        for (int half = 0; half < 2; half++) {
            const int lm = wm + mt*16 + r0 + half*8;
            #pragma unroll
            for (int nt = 0; nt < 8; nt++) {
                const int n0 = wn + nt*8 + c0;
                float v0 = acc[mt][nt][half*2];
                float v1 = acc[mt][nt][half*2 + 1];
                if constexpr (EPI == 1) {
                    if (act) { v0 = featmap(v0); v1 = featmap(v1); }
                    const int t = (bm + lm) & (Tq - 1);
                    const size_t base = ((size_t)bh*Tq + t)*DHq;
                    __half2 h2 = __floats2half2_rn(v0, v1);
                    float2  bk = __half22float2(h2);
                    __half2 l2 = __floats2half2_rn(v0 - bk.x, v1 - bk.y);
                    *(__half2*)&outh[base + n0] = h2;
                    *(__half2*)&outl[base + n0] = l2;
                } else {   // EPI == 5: fp32 partial, pitch DHq
                    *(float2*)(out_f32 + (size_t)lm*DHq + n0) =
                        make_float2(v0, v1);
                }
            }
        }
}

// ---------------------------------------------------------------------------
// kernels
// ---------------------------------------------------------------------------
__global__ __launch_bounds__(512, 1)
void kv_proj_kernel()    // K and V projections (big core, transpose epilogue)
{
    const int h   = blockIdx.x;
    const int bmG = blockIdx.y * 256;
    const int z   = blockIdx.z + 1;          // 1 = K, 2 = V
    const int bh  = ((bmG >> 12) << 4) + h;
    const __half* Wh = g_wh + (size_t)z * Cq * Cq;
    const __half* Wl = g_wl + (size_t)z * Cq * Cq;
    if (z == 1)
        mma_big<2, 2>(g_xh, Wh, Wl, Cq, Cq, bmG, h*128, bh,
                      nullptr, g_kth, g_ktl, true, true);
    else
        mma_big<2, 2>(g_xh, Wh, Wl, Cq, Cq, bmG, h*128, bh,
                      nullptr, g_vth, g_vtl, false, false);
}

// Fused: [0,2048) q-projection (small core 2-prod; 128 m-blocks x 16 heads)
//        | [2048,2304) kv partials | [2304,2304+NWB) cvt Wo
#define QBLK 2048
__global__ __launch_bounds__(256, 2)
void q_kv_cvt_kernel(const float* __restrict__ Wo)
{
    const int idx = blockIdx.x;
    if (idx < QBLK) {
        const int h  = idx & 15;
        const int bm = (idx >> 4) * 128;      // 0..127 -> covers all Mq
        const int bh = ((bm >> 12) << 4) + h;
        mma_small<1, 2>(g_xh, g_xh, g_wh, g_wl,      // Wq at slab 0
                        Cq, Cq, Cq, 0, bm, h*128, bh,
                        nullptr, g_qh, g_ql, nullptr, true);
    } else if (idx < QBLK + 256) {
        const int bh = (idx - QBLK) & 63;
        const int p  = (idx - QBLK) >> 6;
        const size_t o = (size_t)bh * DHq * Tq;
        float* outp = g_kvp + ((size_t)p*BHq + bh) * DHq * DHq;
        mma_small<5, 3>(g_vth + o, g_vtl + o, g_kth + o, g_ktl + o,
                        Tq, Tq, 1024, p*1024, 0, 0, bh,
                        outp, nullptr, nullptr, nullptr, false);
    } else {
        const int i = (idx - QBLK - 256) * 256 + threadIdx.x;
        cvt_store_w(Wo, g_wh + (size_t)3*Cq*Cq, g_wl + (size_t)3*Cq*Cq, i);
    }
}

__global__ void kv_reduce_kernel()
{
    const int i = blockIdx.x * blockDim.x + threadIdx.x;
    const int base = i * 2;
    float s0 = 0.f, s1 = 0.f;
    #pragma unroll
    for (int p = 0; p < 4; p++) {
        const float2 v = *(const float2*)&g_kvp[(size_t)p*BHq*DHq*DHq + base];
        s0 += v.x; s1 += v.y;
    }
    __half2 h2 = __floats2half2_rn(s0, s1);
    float2  bk = __half22float2(h2);
    __half2 l2 = __floats2half2_rn(s0 - bk.x, s1 - bk.y);
    *(__half2*)&g_kvh[base] = h2;
    *(__half2*)&g_kvl[base] = l2;
}

__global__ __launch_bounds__(256, 2)
void attn_mma_kernel()
{
    const int bh = blockIdx.x;
    const int bm = blockIdx.y * 128;
    const size_t oq = (size_t)bh * Tq * DHq;
    const size_t ok = (size_t)bh * DHq * DHq;
    mma_small<4, 3>(g_qh + oq, g_ql + oq, g_kvh + ok, g_kvl + ok,
                    DHq, DHq, DHq, 0, bm, 0, bh,
                    nullptr, g_ath, nullptr, g_ksum + bh*DHq, false);
}

__global__ __launch_bounds__(512, 1)
void out_mma_kernel(float* __restrict__ out)   // 1-product (Wo hi only)
{
    mma_big<0, 1>(g_ath, g_wh + (size_t)3*Cq*Cq, g_wl + (size_t)3*Cq*Cq,
                  Cq, Cq, blockIdx.y*256, blockIdx.x*128, 0,
                  out, nullptr, nullptr, false, false);
}

// ---------------------------------------------------------------------------
extern "C" void kernel_launch(void* const* d_in, const int* in_sizes, int n_in,
                              void* d_out, int out_size)
{
    const float* x  = (const float*)d_in[0];
    // d_in[1] = cos, d_in[2] = sin : unused by the reference module
    const float* Wq = (const float*)d_in[3];
    const float* Wk = (const float*)d_in[4];
    const float* Wv = (const float*)d_in[5];
    const float* Wo = (const float*)d_in[6];
    float* out = (float*)d_out;

    cudaFuncSetAttribute(kv_proj_kernel,
                         cudaFuncAttributeMaxDynamicSharedMemorySize, SMEM_BIG2);
    cudaFuncSetAttribute(q_kv_cvt_kernel,
                         cudaFuncAttributeMaxDynamicSharedMemorySize, SMEM_STD);
    cudaFuncSetAttribute(attn_mma_kernel,
                         cudaFuncAttributeMaxDynamicSharedMemorySize, SMEM_STD);
    cudaFuncSetAttribute(out_mma_kernel,
                         cudaFuncAttributeMaxDynamicSharedMemorySize, SMEM_STD);

    cvt_all_kernel<<<NXB + 3*NWB, 256>>>(x, Wq, Wk, Wv);
    kv_proj_kernel<<<dim3(Hq, Mq/256, 2), 512, SMEM_BIG2>>>();
    q_kv_cvt_kernel<<<QBLK + 256 + NWB, 256, SMEM_STD>>>(Wo);
    kv_reduce_kernel<<<BHq*DHq*DHq/2/256, 256>>>();
    attn_mma_kernel<<<dim3(BHq, Tq/128), 256, SMEM_STD>>>();
    out_mma_kernel<<<dim3(Cq/128, Mq/256), 512, SMEM_STD>>>(out);
}

// round 17
// speedup vs baseline: 1.6082x; 1.4427x over previous
#include <cuda_runtime.h>
#include <cuda_fp16.h>
#include <cstdint>

// Problem constants
#define Bq   4
#define Tq   4096
#define Cq   2048
#define Hq   16
#define DHq  128
#define Mq   (Bq*Tq)          // 16384
#define BHq  (Bq*Hq)          // 64

// -------- device globals (allocation-free rule) --------
__device__ __half g_xh[Mq*Cq];     // x hi [m][c]
__device__ __half g_wh[4*Cq*Cq];   // Wq|Wk|Wv|Wo hi [o][c]
__device__ __half g_qh[Mq*Cq];     // q hi/lo [bh][t][d]
__device__ __half g_ql[Mq*Cq];
__device__ __half g_kth[Mq*Cq];    // kT hi/lo [bh][d][t]
__device__ __half g_ktl[Mq*Cq];
__device__ __half g_vth[Mq*Cq];    // vT hi/lo [bh][d][t]
__device__ __half g_vtl[Mq*Cq];
__device__ float  g_kvp[4*BHq*DHq*DHq];  // kv split-T fp32 partials
__device__ __half g_kvh[BHq*DHq*DHq];    // kvT[e][d] hi/lo
__device__ __half g_kvl[BHq*DHq*DHq];
__device__ __half g_ath[Mq*Cq];    // attention out hi [b,t,C]
__device__ float  g_ksum[BHq*DHq];

__device__ __forceinline__ float featmap(float y) {
    return y > 0.f ? y + 1.f : __expf(y);   // elu(y)+1
}

__device__ __forceinline__ uint32_t smem_u32(const void* p) {
    uint32_t a;
    asm("{ .reg .u64 t; cvta.to.shared.u64 t, %1; cvt.u32.u64 %0, t; }"
        : "=r"(a) : "l"(p));
    return a;
}

__device__ __forceinline__ void cpa16(uint32_t s, const void* g) {
    asm volatile("cp.async.cg.shared.global [%0], [%1], 16;" :: "r"(s), "l"(g));
}

#define LDSM4(r, a)                                                            \
    asm volatile("ldmatrix.sync.aligned.m8n8.x4.shared.b16 {%0,%1,%2,%3}, [%4];" \
        : "=r"((r)[0]), "=r"((r)[1]), "=r"((r)[2]), "=r"((r)[3]) : "r"(a))

__device__ __forceinline__ void mma16816(float* d, const uint32_t* a, const uint32_t* b)
{
    asm volatile(
        "mma.sync.aligned.m16n8k16.row.col.f32.f16.f16.f32 "
        "{%0,%1,%2,%3}, {%4,%5,%6,%7}, {%8,%9}, {%0,%1,%2,%3};"
        : "+f"(d[0]), "+f"(d[1]), "+f"(d[2]), "+f"(d[3])
        : "r"(a[0]), "r"(a[1]), "r"(a[2]), "r"(a[3]), "r"(b[0]), "r"(b[1]));
}

// ===========================================================================
// cvt_all: x -> hi (+ksum zero), W0..W3 -> hi only, one launch.
// ===========================================================================
#define NXB  (Mq*Cq/4/256)   // 32768
#define NWB  (Cq*Cq/4/256)   // 4096

__global__ void cvt_all_kernel(const float* __restrict__ x,
                               const float* __restrict__ Wq,
                               const float* __restrict__ Wk,
                               const float* __restrict__ Wv,
                               const float* __restrict__ Wo)
{
    const int blk = blockIdx.x;
    if (blk < NXB) {
        const int i = blk * 256 + threadIdx.x;
        if (i < BHq*DHq) g_ksum[i] = 0.f;
        float4 v = ((const float4*)x)[i];
        ((__half2*)g_xh)[i*2]   = __floats2half2_rn(v.x, v.y);
        ((__half2*)g_xh)[i*2+1] = __floats2half2_rn(v.z, v.w);
        return;
    }
    const int s = (blk - NXB) / NWB;          // 0..3
    const int i = ((blk - NXB) - s*NWB) * 256 + threadIdx.x;
    const float* src = (s == 0) ? Wq : (s == 1) ? Wk : (s == 2) ? Wv : Wo;
    __half* hi = g_wh + (size_t)s * Cq * Cq;
    float4 v = ((const float4*)src)[i];
    ((__half2*)hi)[i*2]   = __floats2half2_rn(v.x, v.y);
    ((__half2*)hi)[i*2+1] = __floats2half2_rn(v.z, v.w);
}

#define SMEM_STD     98304
#define TPITCH       136

// ===========================================================================
// BIG core: 256x128 CTA, 512 threads (16 warps, 4m x 4n), BK=32, NPROD=1
// (A hi x B hi).  Stage A16K|Bh8K = 24KB, 4 slots, depth 3.
// EPI: 0 = fp32 out; 2 = (act?) -> transpose -> hi/lo [bh][d][t] (+ksum)
// ===========================================================================
template<int EPI>
__device__ __forceinline__ void mma_big(
    const __half* __restrict__ Ah_g, const __half* __restrict__ Bh_g,
    int lda, int ldb, int bmG, int bn, int bh,
    float* __restrict__ out_f32, __half* __restrict__ outh,
    __half* __restrict__ outl, bool act, bool do_ks)
{
    constexpr uint32_t STG = 24576u;

    extern __shared__ char sm2[];
    const uint32_t sb = smem_u32(sm2);
    const int tid = threadIdx.x;

    const int rowG = tid >> 1;
    const int seg0 = (tid & 1) * 2;
    const uint32_t xrg = ((rowG >> 1) & 3) << 4;
    const uint32_t d0 = rowG*64 + (( seg0   *16) ^ xrg);
    const uint32_t d1 = rowG*64 + (((seg0+1)*16) ^ xrg);
    const __half* sA = Ah_g + (size_t)(bmG + rowG) * lda + seg0*8;
    const __half* sB = Bh_g + (size_t)(bn + rowG) * ldb + seg0*8;
    const bool loadB = (rowG < 128);

    auto issue = [&](int kc, int slot) {
        const uint32_t b = sb + slot * STG;
        const int ko = kc * 32;
        cpa16(b          + d0, sA + ko);  cpa16(b          + d1, sA + ko + 8);
        if (loadB) {
            cpa16(b + 16384u + d0, sB + ko);  cpa16(b + 16384u + d1, sB + ko + 8);
        }
        asm volatile("cp.async.commit_group;" ::: "memory");
    };

    issue(0, 0);
    issue(1, 1);
    issue(2, 2);

    const int wid  = tid >> 5;
    const int lane = tid & 31;
    const int wm = (wid & 3) * 64;
    const int wn = (wid >> 2) * 32;
    const uint32_t xs  = ((lane >> 1) & 3) << 4;
    const uint32_t kqa = (lane >> 4) * 16;
    const uint32_t kqb = ((lane >> 3) & 1) * 16;
    uint32_t saofs[4], sbofs[2];
    #pragma unroll
    for (int mt = 0; mt < 4; mt++)
        saofs[mt] = (uint32_t)(wm + mt*16 + (lane & 15)) * 64;
    #pragma unroll
    for (int p = 0; p < 2; p++)
        sbofs[p] = (uint32_t)(wn + p*16 + ((lane >> 4) & 1)*8 + (lane & 7)) * 64;

    float acc[4][4][4];
    #pragma unroll
    for (int i = 0; i < 4; i++)
        #pragma unroll
        for (int j = 0; j < 4; j++)
            #pragma unroll
            for (int e = 0; e < 4; e++) acc[i][j][e] = 0.f;

    const int NCHUNK = Cq / 32;   // 64

    for (int kc = 0; kc < NCHUNK; kc++) {
        if (kc <= NCHUNK - 3)      asm volatile("cp.async.wait_group 2;" ::: "memory");
        else if (kc == NCHUNK - 2) asm volatile("cp.async.wait_group 1;" ::: "memory");
        else                       asm volatile("cp.async.wait_group 0;" ::: "memory");
        __syncthreads();
        if (kc + 3 < NCHUNK) issue(kc + 3, (kc + 3) & 3);

        const uint32_t st = sb + (kc & 3) * STG;
        #pragma unroll
        for (int ks = 0; ks < 2; ks++) {
            uint32_t ah[4][4];
            const uint32_t ca = (ks*32 + kqa) ^ xs;
            #pragma unroll
            for (int mt = 0; mt < 4; mt++)
                LDSM4(ah[mt], st + saofs[mt] + ca);
            const uint32_t cb = (ks*32 + kqb) ^ xs;
            #pragma unroll
            for (int p = 0; p < 2; p++) {
                uint32_t bh2[4];
                LDSM4(bh2, st + 16384u + sbofs[p] + cb);
                #pragma unroll
                for (int mt = 0; mt < 4; mt++) {
                    mma16816(acc[mt][2*p],   ah[mt], bh2);
                    mma16816(acc[mt][2*p+1], ah[mt], bh2 + 2);
                }
            }
        }
    }

    const int r0 = lane >> 2;
    const int c0 = (lane & 3) * 2;

    if constexpr (EPI == 2) {
        __syncthreads();
        __half* shh = (__half*)sm2;
        __half* shl = shh + 128*TPITCH;
        const int myhh = (wid & 3) >> 1;
        const int dd = tid >> 2;
        const int ts = (tid & 3) * 32;
        float ksacc = 0.f;
        #pragma unroll
        for (int hh = 0; hh < 2; hh++) {
            if (myhh == hh) {
                #pragma unroll
                for (int mt = 0; mt < 4; mt++)
                    #pragma unroll
                    for (int half = 0; half < 2; half++) {
                        const int lt = (wm + mt*16 + r0 + half*8) & 127;
                        #pragma unroll
                        for (int nt = 0; nt < 4; nt++) {
                            const int n0 = wn + nt*8 + c0;
                            float v0 = acc[mt][nt][half*2];
                            float v1 = acc[mt][nt][half*2 + 1];
                            if (act) { v0 = featmap(v0); v1 = featmap(v1); }
                            __half h0 = __float2half_rn(v0);
                            __half h1 = __float2half_rn(v1);
                            __half l0 = __float2half_rn(v0 - __half2float(h0));
                            __half l1 = __float2half_rn(v1 - __half2float(h1));
                            shh[ n0   *TPITCH + lt] = h0;
                            shh[(n0+1)*TPITCH + lt] = h1;
                            shl[ n0   *TPITCH + lt] = l0;
                            shl[(n0+1)*TPITCH + lt] = l1;
                        }
                    }
            }
            __syncthreads();
            const int tdst = (bmG & (Tq - 1)) + hh*128 + ts;
            const uint4* srcH = (const uint4*)(shh + dd*TPITCH + ts);
            const uint4* srcL = (const uint4*)(shl + dd*TPITCH + ts);
            uint4* dstH = (uint4*)(outh + ((size_t)bh*DHq + dd)*Tq + tdst);
            uint4* dstL = (uint4*)(outl + ((size_t)bh*DHq + dd)*Tq + tdst);
            #pragma unroll
            for (int q = 0; q < 4; q++) {
                uint4 h4 = srcH[q], l4 = srcL[q];
                dstH[q] = h4; dstL[q] = l4;
                if (do_ks) {
                    const __half2* hp = (const __half2*)&h4;
                    const __half2* lp = (const __half2*)&l4;
                    #pragma unroll
                    for (int e = 0; e < 4; e++) {
                        float2 a = __half22float2(hp[e]);
                        float2 b = __half22float2(lp[e]);
                        ksacc += a.x + a.y + b.x + b.y;
                    }
                }
            }
            __syncthreads();
        }
        if (do_ks) atomicAdd(&g_ksum[bh*DHq + dd], ksacc);
        return;
    }

    // EPI == 0
    #pragma unroll
    for (int mt = 0; mt < 4; mt++)
        #pragma unroll
        for (int half = 0; half < 2; half++) {
            const int lm = wm + mt*16 + r0 + half*8;
            #pragma unroll
            for (int nt = 0; nt < 4; nt++) {
                const int n0 = wn + nt*8 + c0;
                float* op = out_f32 + (size_t)(bmG + lm) * Cq + bn;
                *(float2*)(op + n0) =
                    make_float2(acc[mt][nt][half*2], acc[mt][nt][half*2 + 1]);
            }
        }
}

// ===========================================================================
// Small 128x128 core, 256 threads (8 warps, 4m x 2n).
// NPROD=1: A hi, B hi (16KB stage, 4 slots, depth 3).
// NPROD=3: A hi+lo, B hi+lo (32KB stage, 3 slots, depth 2).
// EPI: 1 = featmap -> q hi/lo; 4 = attn (z in-kernel); 5 = kv fp32 partial.
// ===========================================================================
template<int EPI, int NPROD>
__device__ __forceinline__ void mma_small(
    const __half* __restrict__ Ah_g, const __half* __restrict__ Al_g,
    const __half* __restrict__ Bh_g, const __half* __restrict__ Bl_g,
    int lda, int ldb, int Klen, int koff, int bm, int bn, int bh,
    float* __restrict__ out_f32, __half* __restrict__ outh,
    __half* __restrict__ outl, const float* __restrict__ kss, bool act)
{
    constexpr uint32_t STG  = (NPROD == 3) ? 32768u : 16384u;
    constexpr int      NSTG = (NPROD == 3) ? 3 : 4;
    constexpr uint32_t OBH  = (NPROD == 3) ? 16384u : 8192u;
    constexpr uint32_t OBL  = OBH + 8192u;

    extern __shared__ char sm2[];
    const uint32_t sb = smem_u32(sm2);
    const int tid = threadIdx.x;

    const int rowG = tid >> 1;
    const int seg0 = (tid & 1) * 2;
    const uint32_t xrg = ((rowG >> 1) & 3) << 4;
    const uint32_t d0 = rowG*64 + (( seg0   *16) ^ xrg);
    const uint32_t d1 = rowG*64 + (((seg0+1)*16) ^ xrg);
    const __half* sAh = Ah_g + (size_t)(bm + rowG) * lda + seg0*8 + koff;
    const __half* sAl = Al_g + (size_t)(bm + rowG) * lda + seg0*8 + koff;
    const __half* sBh = Bh_g + (size_t)(bn + rowG) * ldb + seg0*8 + koff;
    const __half* sBl = Bl_g + (size_t)(bn + rowG) * ldb + seg0*8 + koff;

    auto issue = [&](int kc, int slot) {
        const uint32_t b = sb + slot * STG;
        const int ko = kc * 32;
        cpa16(b       + d0, sAh + ko);  cpa16(b       + d1, sAh + ko + 8);
        if (NPROD == 3) {
            cpa16(b + 8192u + d0, sAl + ko);  cpa16(b + 8192u + d1, sAl + ko + 8);
        }
        cpa16(b + OBH + d0, sBh + ko);  cpa16(b + OBH + d1, sBh + ko + 8);
        if (NPROD == 3) {
            cpa16(b + OBL + d0, sBl + ko);  cpa16(b + OBL + d1, sBl + ko + 8);
        }
        asm volatile("cp.async.commit_group;" ::: "memory");
    };

    const int NCHUNK = Klen / 32;

    issue(0, 0);
    issue(1, 1);
    if (NPROD != 3 && NCHUNK > 2) issue(2, 2);

    const int wid  = tid >> 5;
    const int lane = tid & 31;
    const int wm = (wid & 3) * 32;
    const int wn = (wid >> 2) * 64;
    const uint32_t xs  = ((lane >> 1) & 3) << 4;
    const uint32_t kqa = (lane >> 4) * 16;
    const uint32_t kqb = ((lane >> 3) & 1) * 16;
    uint32_t saofs[2], sbofs[4];
    #pragma unroll
    for (int mt = 0; mt < 2; mt++)
        saofs[mt] = (uint32_t)(wm + mt*16 + (lane & 15)) * 64;
    #pragma unroll
    for (int p = 0; p < 4; p++)
        sbofs[p] = (uint32_t)(wn + p*16 + ((lane >> 4) & 1)*8 + (lane & 7)) * 64;

    float acc[2][8][4];
    #pragma unroll
    for (int i = 0; i < 2; i++)
        #pragma unroll
        for (int j = 0; j < 8; j++)
            #pragma unroll
            for (int e = 0; e < 4; e++) acc[i][j][e] = 0.f;

    for (int kc = 0; kc < NCHUNK; kc++) {
        if (NPROD != 3) {
            if (kc < NCHUNK - 2)       asm volatile("cp.async.wait_group 2;" ::: "memory");
            else if (kc == NCHUNK - 2) asm volatile("cp.async.wait_group 1;" ::: "memory");
            else                       asm volatile("cp.async.wait_group 0;" ::: "memory");
        } else {
            if (kc == NCHUNK - 1) asm volatile("cp.async.wait_group 0;" ::: "memory");
            else                  asm volatile("cp.async.wait_group 1;" ::: "memory");
        }
        __syncthreads();
        if (NPROD != 3) { if (kc + 3 < NCHUNK) issue(kc + 3, (kc + 3) % NSTG); }
        else            { if (kc + 2 < NCHUNK) issue(kc + 2, (kc + 2) % NSTG); }

        const uint32_t st = sb + (kc % NSTG) * STG;
        #pragma unroll
        for (int ks = 0; ks < 2; ks++) {
            uint32_t ah[2][4], al[2][4];
            const uint32_t ca = (ks*32 + kqa) ^ xs;
            #pragma unroll
            for (int mt = 0; mt < 2; mt++) {
                LDSM4(ah[mt], st + saofs[mt] + ca);
                if (NPROD == 3) LDSM4(al[mt], st + 8192u + saofs[mt] + ca);
            }
            const uint32_t cb = (ks*32 + kqb) ^ xs;
            #pragma unroll
            for (int p = 0; p < 4; p++) {
                uint32_t bh2[4], bl2[4];
                LDSM4(bh2, st + OBH + sbofs[p] + cb);
                if (NPROD == 3) LDSM4(bl2, st + OBL + sbofs[p] + cb);
                #pragma unroll
                for (int mt = 0; mt < 2; mt++) {
                    mma16816(acc[mt][2*p],   ah[mt], bh2);
                    mma16816(acc[mt][2*p+1], ah[mt], bh2 + 2);
                    if (NPROD == 3) {
                        mma16816(acc[mt][2*p],   ah[mt], bl2);
                        mma16816(acc[mt][2*p],   al[mt], bh2);
                        mma16816(acc[mt][2*p+1], ah[mt], bl2 + 2);
                        mma16816(acc[mt][2*p+1], al[mt], bh2 + 2);
                    }
                }
            }
        }
    }

    const int r0 = lane >> 2;
    const int c0 = (lane & 3) * 2;

    if constexpr (EPI == 4) {
        __syncthreads();
        float* zs = (float*)sm2;
        if (tid < 128) {
            const __half2* qh2 = (const __half2*)(Ah_g + (size_t)(bm + tid)*lda);
            const __half2* ql2 = (const __half2*)(Al_g + (size_t)(bm + tid)*lda);
            const float2* kf = (const float2*)kss;
            float s = 0.f;
            #pragma unroll 16
            for (int i = 0; i < 64; i++) {
                float2 a = __half22float2(qh2[i]);
                float2 b = __half22float2(ql2[i]);
                float2 k2 = kf[i];
                s += (a.x + b.x) * k2.x + (a.y + b.y) * k2.y;
            }
            zs[tid] = 1.f / (s + 1e-6f);
        }
        __syncthreads();
        #pragma unroll
        for (int mt = 0; mt < 2; mt++)
            #pragma unroll
            for (int half = 0; half < 2; half++) {
                const int lm = wm + mt*16 + r0 + half*8;
                const float z = zs[lm];
                const int t = bm + lm;
                const size_t base =
                    ((size_t)(bh >> 4)*Tq + t)*Cq + (size_t)(bh & 15)*DHq;
                #pragma unroll
                for (int nt = 0; nt < 8; nt++) {
                    const int n0 = wn + nt*8 + c0;
                    *(__half2*)&outh[base + n0] =
                        __floats2half2_rn(acc[mt][nt][half*2] * z,
                                          acc[mt][nt][half*2 + 1] * z);
                }
            }
        return;
    }

    #pragma unroll
    for (int mt = 0; mt < 2; mt++)
        #pragma unroll
        for (int half = 0; half < 2; half++) {
            const int lm = wm + mt*16 + r0 + half*8;
            #pragma unroll
            for (int nt = 0; nt < 8; nt++) {
                const int n0 = wn + nt*8 + c0;
                float v0 = acc[mt][nt][half*2];
                float v1 = acc[mt][nt][half*2 + 1];
                if constexpr (EPI == 1) {
                    if (act) { v0 = featmap(v0); v1 = featmap(v1); }
                    const int t = (bm + lm) & (Tq - 1);
                    const size_t base = ((size_t)bh*Tq + t)*DHq;
                    __half2 h2 = __floats2half2_rn(v0, v1);
                    float2  bk = __half22float2(h2);
                    __half2 l2 = __floats2half2_rn(v0 - bk.x, v1 - bk.y);
                    *(__half2*)&outh[base + n0] = h2;
                    *(__half2*)&outl[base + n0] = l2;
                } else {   // EPI == 5: fp32 partial, pitch DHq
                    *(float2*)(out_f32 + (size_t)lm*DHq + n0) =
                        make_float2(v0, v1);
                }
            }
        }
}

// ---------------------------------------------------------------------------
// kernels
// ---------------------------------------------------------------------------
__global__ __launch_bounds__(512, 1)
void kv_proj_kernel()    // K and V projections, 1-product, transpose epilogue
{
    const int h   = blockIdx.x;
    const int bmG = blockIdx.y * 256;
    const int z   = blockIdx.z + 1;          // 1 = K, 2 = V
    const int bh  = ((bmG >> 12) << 4) + h;
    const __half* Wh = g_wh + (size_t)z * Cq * Cq;
    if (z == 1)
        mma_big<2>(g_xh, Wh, Cq, Cq, bmG, h*128, bh,
                   nullptr, g_kth, g_ktl, true, true);
    else
        mma_big<2>(g_xh, Wh, Cq, Cq, bmG, h*128, bh,
                   nullptr, g_vth, g_vtl, false, false);
}

// Fused: [0,2048) q-projection (small 1-prod) | [2048,2304) kv partials
#define QBLK 2048
__global__ __launch_bounds__(256, 2)
void q_kv_kernel()
{
    const int idx = blockIdx.x;
    if (idx < QBLK) {
        const int h  = idx & 15;
        const int bm = (idx >> 4) * 128;      // covers all Mq
        const int bh = ((bm >> 12) << 4) + h;
        mma_small<1, 1>(g_xh, g_xh, g_wh, g_wh,      // Wq at slab 0, hi only
                        Cq, Cq, Cq, 0, bm, h*128, bh,
                        nullptr, g_qh, g_ql, nullptr, true);
    } else {
        const int bh = (idx - QBLK) & 63;
        const int p  = (idx - QBLK) >> 6;
        const size_t o = (size_t)bh * DHq * Tq;
        float* outp = g_kvp + ((size_t)p*BHq + bh) * DHq * DHq;
        mma_small<5, 3>(g_vth + o, g_vtl + o, g_kth + o, g_ktl + o,
                        Tq, Tq, 1024, p*1024, 0, 0, bh,
                        outp, nullptr, nullptr, nullptr, false);
    }
}

__global__ void kv_reduce_kernel()
{
    const int i = blockIdx.x * blockDim.x + threadIdx.x;
    const int base = i * 2;
    float s0 = 0.f, s1 = 0.f;
    #pragma unroll
    for (int p = 0; p < 4; p++) {
        const float2 v = *(const float2*)&g_kvp[(size_t)p*BHq*DHq*DHq + base];
        s0 += v.x; s1 += v.y;
    }
    __half2 h2 = __floats2half2_rn(s0, s1);
    float2  bk = __half22float2(h2);
    __half2 l2 = __floats2half2_rn(s0 - bk.x, s1 - bk.y);
    *(__half2*)&g_kvh[base] = h2;
    *(__half2*)&g_kvl[base] = l2;
}

__global__ __launch_bounds__(256, 2)
void attn_mma_kernel()
{
    const int bh = blockIdx.x;
    const int bm = blockIdx.y * 128;
    const size_t oq = (size_t)bh * Tq * DHq;
    const size_t ok = (size_t)bh * DHq * DHq;
    mma_small<4, 3>(g_qh + oq, g_ql + oq, g_kvh + ok, g_kvl + ok,
                    DHq, DHq, DHq, 0, bm, 0, bh,
                    nullptr, g_ath, nullptr, g_ksum + bh*DHq, false);
}

__global__ __launch_bounds__(512, 1)
void out_mma_kernel(float* __restrict__ out)   // 1-product (Wo hi only)
{
    mma_big<0>(g_ath, g_wh + (size_t)3*Cq*Cq,
               Cq, Cq, blockIdx.y*256, blockIdx.x*128, 0,
               out, nullptr, nullptr, false, false);
}

// ---------------------------------------------------------------------------
extern "C" void kernel_launch(void* const* d_in, const int* in_sizes, int n_in,
                              void* d_out, int out_size)
{
    const float* x  = (const float*)d_in[0];
    // d_in[1] = cos, d_in[2] = sin : unused by the reference module
    const float* Wq = (const float*)d_in[3];
    const float* Wk = (const float*)d_in[4];
    const float* Wv = (const float*)d_in[5];
    const float* Wo = (const float*)d_in[6];
    float* out = (float*)d_out;

    cudaFuncSetAttribute(kv_proj_kernel,
                         cudaFuncAttributeMaxDynamicSharedMemorySize, SMEM_STD);
    cudaFuncSetAttribute(q_kv_kernel,
                         cudaFuncAttributeMaxDynamicSharedMemorySize, SMEM_STD);
    cudaFuncSetAttribute(attn_mma_kernel,
                         cudaFuncAttributeMaxDynamicSharedMemorySize, SMEM_STD);
    cudaFuncSetAttribute(out_mma_kernel,
                         cudaFuncAttributeMaxDynamicSharedMemorySize, SMEM_STD);

    cvt_all_kernel<<<NXB + 4*NWB, 256>>>(x, Wq, Wk, Wv, Wo);
    kv_proj_kernel<<<dim3(Hq, Mq/256, 2), 512, SMEM_STD>>>();
    q_kv_kernel<<<QBLK + 256, 256, SMEM_STD>>>();
    kv_reduce_kernel<<<BHq*DHq*DHq/2/256, 256>>>();
    attn_mma_kernel<<<dim3(BHq, Tq/128), 256, SMEM_STD>>>();
    out_mma_kernel<<<dim3(Cq/128, Mq/256), 512, SMEM_STD>>>(out);
}